// round 4
// baseline (speedup 1.0000x reference)
#include <cuda_runtime.h>
#include <math.h>
#include <stdint.h>

// ---------------- problem constants ----------------
#define NMAX 200000
#define B_   4
#define C2D  128
#define H_   96
#define W_   312
#define MID  128
#define C3D  64
#define ROWS_BLK 256

typedef unsigned long long ull;

// packed fp32x2 FMA (sm_103a FFMA2)
__device__ __forceinline__ void fma2(ull& d, ull a, ull b) {
    asm("fma.rn.f32x2 %0, %1, %2, %0;" : "+l"(d) : "l"(a), "l"(b));
}
__device__ __forceinline__ float upsum(ull a) {
    float lo, hi;
    asm("mov.b64 {%0,%1}, %2;" : "=f"(lo), "=f"(hi) : "l"(a));
    return lo + hi;
}

// ---------------- scratch ----------------
__device__ __align__(16) float g_imgT[(size_t)B_ * H_ * W_ * C2D];
__device__ __align__(16) float g_hpre[(size_t)NMAX * MID];
__device__ __align__(16) float g_vfeat[(size_t)NMAX * MID];
__device__ __align__(16) float g_ifeat[(size_t)NMAX * C2D];
__device__ float g_att[NMAX];
__device__ float g_stats[512];
__device__ float g_bnp[512];

__global__ void k_zero() {
    if (threadIdx.x < 512) g_stats[threadIdx.x] = 0.f;
}

// ---------------- K0: image transpose [B,C,H,W] -> [B,H,W,C] ----------------
__global__ void k_transpose(const float* __restrict__ img) {
    __shared__ float tile[32][33];
    int bh = blockIdx.z;
    int b  = bh / H_;
    int hh = bh % H_;
    int w0 = blockIdx.x * 32;
    int c0 = blockIdx.y * 32;
    int tx = threadIdx.x, ty = threadIdx.y;
    #pragma unroll
    for (int i = 0; i < 32; i += 8) {
        int c = c0 + ty + i;
        int w = w0 + tx;
        float v = 0.f;
        if (w < W_) v = img[((size_t)(b * C2D + c) * H_ + hh) * W_ + w];
        tile[ty + i][tx] = v;
    }
    __syncthreads();
    #pragma unroll
    for (int i = 0; i < 32; i += 8) {
        int w = w0 + ty + i;
        int c = c0 + tx;
        if (w < W_)
            g_imgT[((size_t)bh * W_ + w) * C2D + c] = tile[tx][ty + i];
    }
}

// ---------------- K1: hpre = vf @ w1^T + b1, bn1 stats ----------------
// 256 threads: j = t>>1 (output col), h = t&1 (K half, 32 floats each)
__global__ __launch_bounds__(256) void k_gemm1(const float* __restrict__ vf,
                                               const float* __restrict__ w1,
                                               const float* __restrict__ b1,
                                               int N) {
    int t = threadIdx.x;
    int j = t >> 1, h = t & 1;
    ull w[16];
    const ulonglong2* wp = reinterpret_cast<const ulonglong2*>(w1 + (size_t)j * C3D + h * 32);
    #pragma unroll
    for (int k = 0; k < 8; k++) { ulonglong2 v = wp[k]; w[2*k] = v.x; w[2*k+1] = v.y; }
    float bias = __ldg(b1 + j);
    __shared__ __align__(16) float sx[8][C3D];
    float ssum = 0.f, ssq = 0.f;
    int row0 = blockIdx.x * ROWS_BLK;
    int ntile = (N - row0 + 7) / 8; if (ntile > ROWS_BLK / 8) ntile = ROWS_BLK / 8;

    int lr = t >> 4, lc = (t & 15) * 4;
    float4 pf = make_float4(0.f, 0.f, 0.f, 0.f);
    if (t < 128 && row0 + lr < N)
        pf = *reinterpret_cast<const float4*>(vf + (size_t)(row0 + lr) * C3D + lc);

    for (int tl = 0; tl < ntile; tl++) {
        int base = row0 + tl * 8;
        if (t < 128) *reinterpret_cast<float4*>(&sx[lr][lc]) = pf;
        __syncthreads();
        int nb = base + 8;
        if (t < 128 && tl + 1 < ntile) {
            pf = make_float4(0.f, 0.f, 0.f, 0.f);
            if (nb + lr < N)
                pf = *reinterpret_cast<const float4*>(vf + (size_t)(nb + lr) * C3D + lc);
        }
        #pragma unroll
        for (int r = 0; r < 8; r++) {
            ull a0 = 0, a1 = 0;
            const ulonglong2* xp = reinterpret_cast<const ulonglong2*>(&sx[r][h * 32]);
            #pragma unroll
            for (int k = 0; k < 4; k++) {
                ulonglong2 x0 = xp[2*k], x1 = xp[2*k+1];
                fma2(a0, w[4*k],   x0.x);
                fma2(a1, w[4*k+1], x0.y);
                fma2(a0, w[4*k+2], x1.x);
                fma2(a1, w[4*k+3], x1.y);
            }
            float s = upsum(a0) + upsum(a1);
            s += __shfl_xor_sync(0xffffffffu, s, 1);
            if (h == 0 && base + r < N) {
                float acc = s + bias;
                g_hpre[(size_t)(base + r) * MID + j] = acc;
                ssum += acc; ssq += acc * acc;
            }
        }
        __syncthreads();
    }
    if (h == 0) {
        atomicAdd(&g_stats[j], ssum);
        atomicAdd(&g_stats[128 + j], ssq);
    }
}

// ---------------- finalize bn stats ----------------
__global__ void k_fin(int which, const float* __restrict__ g,
                      const float* __restrict__ b, int N) {
    int j = threadIdx.x;
    int o = which * 256;
    float invN = 1.f / (float)N;
    float m   = g_stats[o + j] * invN;
    float msq = g_stats[o + 128 + j] * invN;
    float var = msq - m * m;
    float s = __ldg(g + j) * rsqrtf(var + 1e-5f);
    g_bnp[o + j] = s;
    g_bnp[o + 128 + j] = __ldg(b + j) - m * s;
}

// ---------------- K3: vfeat = relu(bn(hpre)) @ w2^T + b2 ----------------
// 256 threads: j = t>>1, h = t&1 (64 floats each)
__global__ __launch_bounds__(256) void k_gemm2(const float* __restrict__ w2,
                                               const float* __restrict__ b2,
                                               int N) {
    int t = threadIdx.x;
    int j = t >> 1, h = t & 1;
    ull w[32];
    const ulonglong2* wp = reinterpret_cast<const ulonglong2*>(w2 + (size_t)j * MID + h * 64);
    #pragma unroll
    for (int k = 0; k < 16; k++) { ulonglong2 v = wp[k]; w[2*k] = v.x; w[2*k+1] = v.y; }
    float bias = __ldg(b2 + j);
    int lr = t >> 5, lc = (t & 31) * 4;
    float s0 = g_bnp[lc],     s1 = g_bnp[lc+1],     s2 = g_bnp[lc+2],     s3 = g_bnp[lc+3];
    float h0 = g_bnp[128+lc], h1 = g_bnp[128+lc+1], h2 = g_bnp[128+lc+2], h3 = g_bnp[128+lc+3];
    __shared__ __align__(16) float sx[8][MID];
    int row0 = blockIdx.x * ROWS_BLK;
    int ntile = (N - row0 + 7) / 8; if (ntile > ROWS_BLK / 8) ntile = ROWS_BLK / 8;

    float4 pf = make_float4(0.f, 0.f, 0.f, 0.f);
    if (row0 + lr < N)
        pf = *reinterpret_cast<const float4*>(g_hpre + (size_t)(row0 + lr) * MID + lc);

    for (int tl = 0; tl < ntile; tl++) {
        int base = row0 + tl * 8;
        {
            float4 v = pf;
            v.x = fmaxf(fmaf(v.x, s0, h0), 0.f);
            v.y = fmaxf(fmaf(v.y, s1, h1), 0.f);
            v.z = fmaxf(fmaf(v.z, s2, h2), 0.f);
            v.w = fmaxf(fmaf(v.w, s3, h3), 0.f);
            *reinterpret_cast<float4*>(&sx[lr][lc]) = v;
        }
        __syncthreads();
        int nb = base + 8;
        if (tl + 1 < ntile) {
            pf = make_float4(0.f, 0.f, 0.f, 0.f);
            if (nb + lr < N)
                pf = *reinterpret_cast<const float4*>(g_hpre + (size_t)(nb + lr) * MID + lc);
        }
        #pragma unroll
        for (int r = 0; r < 8; r++) {
            ull a0 = 0, a1 = 0, a2 = 0, a3 = 0;
            const ulonglong2* xp = reinterpret_cast<const ulonglong2*>(&sx[r][h * 64]);
            #pragma unroll
            for (int k = 0; k < 8; k++) {
                ulonglong2 x0 = xp[2*k], x1 = xp[2*k+1];
                fma2(a0, w[4*k],   x0.x);
                fma2(a1, w[4*k+1], x0.y);
                fma2(a2, w[4*k+2], x1.x);
                fma2(a3, w[4*k+3], x1.y);
            }
            float s = (upsum(a0) + upsum(a1)) + (upsum(a2) + upsum(a3));
            s += __shfl_xor_sync(0xffffffffu, s, 1);
            if (h == 0 && base + r < N)
                g_vfeat[(size_t)(base + r) * MID + j] = s + bias;
        }
        __syncthreads();
    }
}

// ---------------- K4: projection + bilinear gather -> ifeat ----------------
__global__ __launch_bounds__(256) void k_sample(const int* __restrict__ coords,
                                                const float* __restrict__ P2,
                                                int N) {
    int j  = threadIdx.x & 127;
    int rr = threadIdx.x >> 7;
    int row0 = blockIdx.x * 64;
    for (int r = rr; r < 64; r += 2) {
        int row = row0 + r;
        if (row >= N) break;
        int4 c4 = __ldg(reinterpret_cast<const int4*>(coords + (size_t)row * 4));
        int b = c4.x;
        float p0 = (float)c4.y * 0.05f;
        float p1 = (float)c4.z * 0.05f - 40.f;
        float p2 = (float)c4.w * 0.1f  - 3.f;
        const float* P = P2 + b * 12;
        float cam0 = __ldg(P+0)*p0 + __ldg(P+1)*p1 + __ldg(P+2)*p2  + __ldg(P+3);
        float cam1 = __ldg(P+4)*p0 + __ldg(P+5)*p1 + __ldg(P+6)*p2  + __ldg(P+7);
        float cam2 = __ldg(P+8)*p0 + __ldg(P+9)*p1 + __ldg(P+10)*p2 + __ldg(P+11);
        float d = cam2 + 1e-8f;
        float u = cam0 / d;
        float v = cam1 / d;
        float gx = u / (float)W_ * 2.f - 1.f; gx = fminf(fmaxf(gx, -1.f), 1.f);
        float gy = v / (float)H_ * 2.f - 1.f; gy = fminf(fmaxf(gy, -1.f), 1.f);
        float ix = ((gx + 1.f) * (float)W_ - 1.f) * 0.5f;
        float iy = ((gy + 1.f) * (float)H_ - 1.f) * 0.5f;
        float x0f = floorf(ix), y0f = floorf(iy);
        float wx = ix - x0f, wy = iy - y0f;
        int x0 = (int)x0f, y0 = (int)y0f;
        float acc = 0.f;
        #pragma unroll
        for (int cy = 0; cy < 2; cy++) {
            #pragma unroll
            for (int cx = 0; cx < 2; cx++) {
                int yc = y0 + cy, xc = x0 + cx;
                float wgt = (cx ? wx : 1.f - wx) * (cy ? wy : 1.f - wy);
                if (xc >= 0 && xc < W_ && yc >= 0 && yc < H_) {
                    acc = fmaf(wgt,
                               g_imgT[(((size_t)(b * H_ + yc)) * W_ + xc) * C2D + j],
                               acc);
                }
            }
        }
        g_ifeat[(size_t)row * C2D + j] = acc;
    }
}

// ---------------- K5: attention scalar ----------------
// 512 threads: j = t>>2 (output col), q = t&3 (K quarter, 64 floats = 32 ull)
__global__ __launch_bounds__(512) void k_att(const float* __restrict__ aw1,
                                             const float* __restrict__ ab1,
                                             const float* __restrict__ aw2,
                                             const float* __restrict__ ab2,
                                             int N) {
    int t = threadIdx.x;
    int j = t >> 2, q = t & 3;
    ull w[32];                                        // FIX: 64 floats per quarter
    const ulonglong2* wp = reinterpret_cast<const ulonglong2*>(aw1 + (size_t)j * 256 + q * 64);
    #pragma unroll
    for (int k = 0; k < 16; k++) { ulonglong2 v = wp[k]; w[2*k] = v.x; w[2*k+1] = v.y; }
    float bj  = __ldg(ab1 + j);
    float w2j = (q == 0) ? __ldg(aw2 + j) : 0.f;
    float b2  = __ldg(ab2);
    __shared__ __align__(16) float sc[8][256];
    __shared__ float srow[8];
    int row0 = blockIdx.x * ROWS_BLK;
    int ntile = (N - row0 + 7) / 8; if (ntile > ROWS_BLK / 8) ntile = ROWS_BLK / 8;

    int lr = t >> 6, lc = (t & 63) * 4;
    float4 pf = make_float4(0.f, 0.f, 0.f, 0.f);
    if (row0 + lr < N) {
        pf = (lc < 128)
           ? *reinterpret_cast<const float4*>(g_vfeat + (size_t)(row0 + lr) * 128 + lc)
           : *reinterpret_cast<const float4*>(g_ifeat + (size_t)(row0 + lr) * 128 + lc - 128);
    }

    for (int tl = 0; tl < ntile; tl++) {
        int base = row0 + tl * 8;
        *reinterpret_cast<float4*>(&sc[lr][lc]) = pf;
        if (t < 8) srow[t] = b2;
        __syncthreads();
        int nb = base + 8;
        if (tl + 1 < ntile) {
            pf = make_float4(0.f, 0.f, 0.f, 0.f);
            if (nb + lr < N) {
                pf = (lc < 128)
                   ? *reinterpret_cast<const float4*>(g_vfeat + (size_t)(nb + lr) * 128 + lc)
                   : *reinterpret_cast<const float4*>(g_ifeat + (size_t)(nb + lr) * 128 + lc - 128);
            }
        }
        float p[8];
        #pragma unroll
        for (int r = 0; r < 8; r++) {
            ull a0 = 0, a1 = 0, a2 = 0, a3 = 0;
            const ulonglong2* xp = reinterpret_cast<const ulonglong2*>(&sc[r][q * 64]);
            #pragma unroll
            for (int k = 0; k < 8; k++) {
                ulonglong2 x0 = xp[2*k], x1 = xp[2*k+1];
                fma2(a0, w[4*k],   x0.x);
                fma2(a1, w[4*k+1], x0.y);
                fma2(a2, w[4*k+2], x1.x);
                fma2(a3, w[4*k+3], x1.y);
            }
            float s = (upsum(a0) + upsum(a1)) + (upsum(a2) + upsum(a3));
            s += __shfl_xor_sync(0xffffffffu, s, 1);
            s += __shfl_xor_sync(0xffffffffu, s, 2);
            p[r] = fmaxf(s + bj, 0.f) * w2j;
        }
        #pragma unroll
        for (int r = 0; r < 8; r++) {
            float v = p[r];
            #pragma unroll
            for (int o = 16; o > 0; o >>= 1) v += __shfl_xor_sync(0xffffffffu, v, o);
            if ((t & 31) == 0) atomicAdd(&srow[r], v);
        }
        __syncthreads();
        if (t < 8 && base + t < N)
            g_att[base + t] = 1.f / (1.f + expf(-srow[t]));
        __syncthreads();
    }
}

// ---------------- K6: fused GEMM -> out_pre, bnf stats ----------------
// 512 threads: j = t>>2, q = t&3.  q{0,1}=vfeat cols, q{2,3}=ifeat cols.
__global__ __launch_bounds__(512) void k_fuse(const float* __restrict__ fw,
                                              const float* __restrict__ fb,
                                              float* __restrict__ out,
                                              int N) {
    int t = threadIdx.x;
    int j = t >> 2, q = t & 3;
    ull w[32];                                        // FIX: 64 floats per quarter
    const ulonglong2* wp = reinterpret_cast<const ulonglong2*>(fw + (size_t)j * 256 + q * 64);
    #pragma unroll
    for (int k = 0; k < 16; k++) { ulonglong2 v = wp[k]; w[2*k] = v.x; w[2*k+1] = v.y; }
    float bias = __ldg(fb + j);
    __shared__ __align__(16) float sc[8][256];
    __shared__ float sa[8];
    float ssum = 0.f, ssq = 0.f;
    int row0 = blockIdx.x * ROWS_BLK;
    int ntile = (N - row0 + 7) / 8; if (ntile > ROWS_BLK / 8) ntile = ROWS_BLK / 8;

    int lr = t >> 6, lc = (t & 63) * 4;
    float4 pf = make_float4(0.f, 0.f, 0.f, 0.f);
    if (row0 + lr < N) {
        pf = (lc < 128)
           ? *reinterpret_cast<const float4*>(g_vfeat + (size_t)(row0 + lr) * 128 + lc)
           : *reinterpret_cast<const float4*>(g_ifeat + (size_t)(row0 + lr) * 128 + lc - 128);
    }

    for (int tl = 0; tl < ntile; tl++) {
        int base = row0 + tl * 8;
        *reinterpret_cast<float4*>(&sc[lr][lc]) = pf;
        if (t < 8) sa[t] = (base + t < N) ? g_att[base + t] : 0.f;
        __syncthreads();
        int nb = base + 8;
        if (tl + 1 < ntile) {
            pf = make_float4(0.f, 0.f, 0.f, 0.f);
            if (nb + lr < N) {
                pf = (lc < 128)
                   ? *reinterpret_cast<const float4*>(g_vfeat + (size_t)(nb + lr) * 128 + lc)
                   : *reinterpret_cast<const float4*>(g_ifeat + (size_t)(nb + lr) * 128 + lc - 128);
            }
        }
        #pragma unroll
        for (int r = 0; r < 8; r++) {
            ull a0 = 0, a1 = 0, a2 = 0, a3 = 0;
            const ulonglong2* xp = reinterpret_cast<const ulonglong2*>(&sc[r][q * 64]);
            #pragma unroll
            for (int k = 0; k < 8; k++) {
                ulonglong2 x0 = xp[2*k], x1 = xp[2*k+1];
                fma2(a0, w[4*k],   x0.x);
                fma2(a1, w[4*k+1], x0.y);
                fma2(a2, w[4*k+2], x1.x);
                fma2(a3, w[4*k+3], x1.y);
            }
            float p = (upsum(a0) + upsum(a1)) + (upsum(a2) + upsum(a3));
            float s2 = p + __shfl_xor_sync(0xffffffffu, p, 1);   // q0:v-part, q2:i-part
            float cr = __shfl_xor_sync(0xffffffffu, s2, 2);      // q0: i-part
            if (q == 0 && base + r < N) {
                float a = sa[r];
                float o = fmaf(a, s2, fmaf(1.f - a, cr, bias));
                out[(size_t)(base + r) * 128 + j] = o;
                ssum += o; ssq += o * o;
            }
        }
        __syncthreads();
    }
    if (q == 0) {
        atomicAdd(&g_stats[256 + j], ssum);
        atomicAdd(&g_stats[384 + j], ssq);
    }
}

// ---------------- K8: in-place final bn + relu ----------------
__global__ void k_bnrelu(float* __restrict__ out, long total4) {
    long i = (long)blockIdx.x * blockDim.x + threadIdx.x;
    if (i < total4) {
        int cb = (int)((i & 31) * 4);
        float4 v = reinterpret_cast<float4*>(out)[i];
        v.x = fmaxf(fmaf(v.x, g_bnp[256 + cb],     g_bnp[384 + cb]),     0.f);
        v.y = fmaxf(fmaf(v.y, g_bnp[256 + cb + 1], g_bnp[384 + cb + 1]), 0.f);
        v.z = fmaxf(fmaf(v.z, g_bnp[256 + cb + 2], g_bnp[384 + cb + 2]), 0.f);
        v.w = fmaxf(fmaf(v.w, g_bnp[256 + cb + 3], g_bnp[384 + cb + 3]), 0.f);
        reinterpret_cast<float4*>(out)[i] = v;
    }
}

// ---------------- launch ----------------
extern "C" void kernel_launch(void* const* d_in, const int* in_sizes, int n_in,
                              void* d_out, int out_size) {
    const float* vf     = (const float*)d_in[0];
    const int*   coords = (const int*)  d_in[1];
    const float* img    = (const float*)d_in[2];
    const float* P2     = (const float*)d_in[3];
    const float* vt_w1  = (const float*)d_in[4];
    const float* vt_b1  = (const float*)d_in[5];
    const float* bn1_g  = (const float*)d_in[6];
    const float* bn1_b  = (const float*)d_in[7];
    const float* vt_w2  = (const float*)d_in[8];
    const float* vt_b2  = (const float*)d_in[9];
    const float* att_w1 = (const float*)d_in[10];
    const float* att_b1 = (const float*)d_in[11];
    const float* att_w2 = (const float*)d_in[12];
    const float* att_b2 = (const float*)d_in[13];
    const float* fus_w  = (const float*)d_in[14];
    const float* fus_b  = (const float*)d_in[15];
    const float* bnf_g  = (const float*)d_in[16];
    const float* bnf_b  = (const float*)d_in[17];

    int N = in_sizes[1] / 4;
    float* out = (float*)d_out;
    int nblk = (N + ROWS_BLK - 1) / ROWS_BLK;

    k_transpose<<<dim3((W_ + 31) / 32, C2D / 32, B_ * H_), dim3(32, 8)>>>(img);
    k_zero<<<1, 512>>>();
    k_gemm1<<<nblk, 256>>>(vf, vt_w1, vt_b1, N);
    k_fin<<<1, 128>>>(0, bn1_g, bn1_b, N);
    k_gemm2<<<nblk, 256>>>(vt_w2, vt_b2, N);
    k_sample<<<(N + 63) / 64, 256>>>(coords, P2, N);
    k_att<<<nblk, 512>>>(att_w1, att_b1, att_w2, att_b2, N);
    k_fuse<<<nblk, 512>>>(fus_w, fus_b, out, N);
    k_fin<<<1, 128>>>(1, bnf_g, bnf_b, N);
    long total4 = (long)N * 32;
    k_bnrelu<<<(unsigned)((total4 + 255) / 256), 256>>>(out, total4);
}

// round 5
// speedup vs baseline: 2.8942x; 2.8942x over previous
#include <cuda_runtime.h>
#include <math.h>
#include <stdint.h>

// ---------------- problem constants ----------------
#define NMAX 200000
#define B_   4
#define C2D  128
#define H_   96
#define W_   312
#define MID  128
#define C3D  64
#define ROWS_BLK 256

typedef unsigned long long ull;

// packed fp32x2 FMA (sm_103a FFMA2)
__device__ __forceinline__ void fma2(ull& d, ull a, ull b) {
    asm("fma.rn.f32x2 %0, %1, %2, %0;" : "+l"(d) : "l"(a), "l"(b));
}
__device__ __forceinline__ float upsum(ull a) {
    float lo, hi;
    asm("mov.b64 {%0,%1}, %2;" : "=f"(lo), "=f"(hi) : "l"(a));
    return lo + hi;
}

// ---------------- scratch ----------------
__device__ __align__(16) float g_imgT[(size_t)B_ * H_ * W_ * C2D];
__device__ __align__(16) float g_hpre[(size_t)NMAX * MID];
__device__ __align__(16) float g_vfeat[(size_t)NMAX * MID];
__device__ __align__(16) float g_ifeat[(size_t)NMAX * C2D];
__device__ float g_att[NMAX];
__device__ float g_stats[512];
__device__ float g_bnp[512];

__global__ void k_zero() {
    if (threadIdx.x < 512) g_stats[threadIdx.x] = 0.f;
}

// ---------------- K0: image transpose [B,C,H,W] -> [B,H,W,C] ----------------
__global__ void k_transpose(const float* __restrict__ img) {
    __shared__ float tile[32][33];
    int bh = blockIdx.z;
    int b  = bh / H_;
    int hh = bh % H_;
    int w0 = blockIdx.x * 32;
    int c0 = blockIdx.y * 32;
    int tx = threadIdx.x, ty = threadIdx.y;
    #pragma unroll
    for (int i = 0; i < 32; i += 8) {
        int c = c0 + ty + i;
        int w = w0 + tx;
        float v = 0.f;
        if (w < W_) v = img[((size_t)(b * C2D + c) * H_ + hh) * W_ + w];
        tile[ty + i][tx] = v;
    }
    __syncthreads();
    #pragma unroll
    for (int i = 0; i < 32; i += 8) {
        int w = w0 + ty + i;
        int c = c0 + tx;
        if (w < W_)
            g_imgT[((size_t)bh * W_ + w) * C2D + c] = tile[tx][ty + i];
    }
}

// ---------------- K1: hpre = vf @ w1^T + b1, bn1 stats ----------------
// 128 threads, j = output col, full K=64 per thread. Register prefetch.
__global__ __launch_bounds__(128) void k_gemm1(const float* __restrict__ vf,
                                               const float* __restrict__ w1,
                                               const float* __restrict__ b1,
                                               int N) {
    int j = threadIdx.x;
    ull w[32];
    const ulonglong2* wp = reinterpret_cast<const ulonglong2*>(w1 + (size_t)j * C3D);
    #pragma unroll
    for (int k = 0; k < 16; k++) { ulonglong2 v = wp[k]; w[2*k] = v.x; w[2*k+1] = v.y; }
    float bias = __ldg(b1 + j);
    __shared__ __align__(16) float sx[8][C3D];
    float ssum = 0.f, ssq = 0.f;
    int row0 = blockIdx.x * ROWS_BLK;
    int ntile = (N - row0 + 7) / 8; if (ntile > ROWS_BLK / 8) ntile = ROWS_BLK / 8;

    int lr = j >> 4, lc = (j & 15) * 4;
    float4 pf = make_float4(0.f, 0.f, 0.f, 0.f);
    if (row0 + lr < N)
        pf = *reinterpret_cast<const float4*>(vf + (size_t)(row0 + lr) * C3D + lc);

    for (int tl = 0; tl < ntile; tl++) {
        int base = row0 + tl * 8;
        *reinterpret_cast<float4*>(&sx[lr][lc]) = pf;
        __syncthreads();
        if (tl + 1 < ntile) {
            int nb = base + 8;
            pf = make_float4(0.f, 0.f, 0.f, 0.f);
            if (nb + lr < N)
                pf = *reinterpret_cast<const float4*>(vf + (size_t)(nb + lr) * C3D + lc);
        }
        #pragma unroll
        for (int r = 0; r < 8; r++) {
            ull a0 = 0, a1 = 0, a2 = 0, a3 = 0;
            const ulonglong2* xp = reinterpret_cast<const ulonglong2*>(&sx[r][0]);
            #pragma unroll
            for (int k = 0; k < 8; k++) {
                ulonglong2 x0 = xp[2*k], x1 = xp[2*k+1];
                fma2(a0, w[4*k],   x0.x);
                fma2(a1, w[4*k+1], x0.y);
                fma2(a2, w[4*k+2], x1.x);
                fma2(a3, w[4*k+3], x1.y);
            }
            if (base + r < N) {
                float acc = bias + ((upsum(a0) + upsum(a1)) + (upsum(a2) + upsum(a3)));
                g_hpre[(size_t)(base + r) * MID + j] = acc;
                ssum += acc; ssq += acc * acc;
            }
        }
        __syncthreads();
    }
    atomicAdd(&g_stats[j], ssum);
    atomicAdd(&g_stats[128 + j], ssq);
}

// ---------------- finalize bn stats ----------------
__global__ void k_fin(int which, const float* __restrict__ g,
                      const float* __restrict__ b, int N) {
    int j = threadIdx.x;
    int o = which * 256;
    float invN = 1.f / (float)N;
    float m   = g_stats[o + j] * invN;
    float msq = g_stats[o + 128 + j] * invN;
    float var = msq - m * m;
    float s = __ldg(g + j) * rsqrtf(var + 1e-5f);
    g_bnp[o + j] = s;
    g_bnp[o + 128 + j] = __ldg(b + j) - m * s;
}

// ---------------- K3: vfeat = relu(bn(hpre)) @ w2^T + b2 ----------------
// 128 threads, full K=128 per thread. Register prefetch (2 float4/thread).
__global__ __launch_bounds__(128) void k_gemm2(const float* __restrict__ w2,
                                               const float* __restrict__ b2,
                                               int N) {
    int j = threadIdx.x;
    ull w[64];
    const ulonglong2* wp = reinterpret_cast<const ulonglong2*>(w2 + (size_t)j * MID);
    #pragma unroll
    for (int k = 0; k < 32; k++) { ulonglong2 v = wp[k]; w[2*k] = v.x; w[2*k+1] = v.y; }
    float bias = __ldg(b2 + j);
    int lr = j >> 5, lc = (j & 31) * 4;
    float s0 = g_bnp[lc],     s1 = g_bnp[lc+1],     s2 = g_bnp[lc+2],     s3 = g_bnp[lc+3];
    float h0 = g_bnp[128+lc], h1 = g_bnp[128+lc+1], h2 = g_bnp[128+lc+2], h3 = g_bnp[128+lc+3];
    __shared__ __align__(16) float sx[8][MID];
    int row0 = blockIdx.x * ROWS_BLK;
    int ntile = (N - row0 + 7) / 8; if (ntile > ROWS_BLK / 8) ntile = ROWS_BLK / 8;

    float4 pf0 = make_float4(0.f,0.f,0.f,0.f), pf1 = pf0;
    if (row0 + lr < N)
        pf0 = *reinterpret_cast<const float4*>(g_hpre + (size_t)(row0 + lr) * MID + lc);
    if (row0 + lr + 4 < N)
        pf1 = *reinterpret_cast<const float4*>(g_hpre + (size_t)(row0 + lr + 4) * MID + lc);

    for (int tl = 0; tl < ntile; tl++) {
        int base = row0 + tl * 8;
        {
            float4 v = pf0;
            v.x = fmaxf(fmaf(v.x, s0, h0), 0.f);
            v.y = fmaxf(fmaf(v.y, s1, h1), 0.f);
            v.z = fmaxf(fmaf(v.z, s2, h2), 0.f);
            v.w = fmaxf(fmaf(v.w, s3, h3), 0.f);
            *reinterpret_cast<float4*>(&sx[lr][lc]) = v;
            v = pf1;
            v.x = fmaxf(fmaf(v.x, s0, h0), 0.f);
            v.y = fmaxf(fmaf(v.y, s1, h1), 0.f);
            v.z = fmaxf(fmaf(v.z, s2, h2), 0.f);
            v.w = fmaxf(fmaf(v.w, s3, h3), 0.f);
            *reinterpret_cast<float4*>(&sx[lr + 4][lc]) = v;
        }
        __syncthreads();
        if (tl + 1 < ntile) {
            int nb = base + 8;
            pf0 = make_float4(0.f,0.f,0.f,0.f); pf1 = pf0;
            if (nb + lr < N)
                pf0 = *reinterpret_cast<const float4*>(g_hpre + (size_t)(nb + lr) * MID + lc);
            if (nb + lr + 4 < N)
                pf1 = *reinterpret_cast<const float4*>(g_hpre + (size_t)(nb + lr + 4) * MID + lc);
        }
        #pragma unroll
        for (int r = 0; r < 8; r++) {
            if (base + r < N) {
                ull a0 = 0, a1 = 0, a2 = 0, a3 = 0;
                const ulonglong2* xp = reinterpret_cast<const ulonglong2*>(&sx[r][0]);
                #pragma unroll
                for (int k = 0; k < 16; k++) {
                    ulonglong2 x0 = xp[2*k], x1 = xp[2*k+1];
                    fma2(a0, w[4*k],   x0.x);
                    fma2(a1, w[4*k+1], x0.y);
                    fma2(a2, w[4*k+2], x1.x);
                    fma2(a3, w[4*k+3], x1.y);
                }
                g_vfeat[(size_t)(base + r) * MID + j] =
                    bias + ((upsum(a0) + upsum(a1)) + (upsum(a2) + upsum(a3)));
            }
        }
        __syncthreads();
    }
}

// ---------------- K4: projection + bilinear gather -> ifeat ----------------
__global__ __launch_bounds__(256) void k_sample(const int* __restrict__ coords,
                                                const float* __restrict__ P2,
                                                int N) {
    int j  = threadIdx.x & 127;
    int rr = threadIdx.x >> 7;
    int row0 = blockIdx.x * 64;
    for (int r = rr; r < 64; r += 2) {
        int row = row0 + r;
        if (row >= N) break;
        int4 c4 = __ldg(reinterpret_cast<const int4*>(coords + (size_t)row * 4));
        int b = c4.x;
        float p0 = (float)c4.y * 0.05f;
        float p1 = (float)c4.z * 0.05f - 40.f;
        float p2 = (float)c4.w * 0.1f  - 3.f;
        const float* P = P2 + b * 12;
        float cam0 = __ldg(P+0)*p0 + __ldg(P+1)*p1 + __ldg(P+2)*p2  + __ldg(P+3);
        float cam1 = __ldg(P+4)*p0 + __ldg(P+5)*p1 + __ldg(P+6)*p2  + __ldg(P+7);
        float cam2 = __ldg(P+8)*p0 + __ldg(P+9)*p1 + __ldg(P+10)*p2 + __ldg(P+11);
        float d = cam2 + 1e-8f;
        float u = cam0 / d;
        float v = cam1 / d;
        float gx = u / (float)W_ * 2.f - 1.f; gx = fminf(fmaxf(gx, -1.f), 1.f);
        float gy = v / (float)H_ * 2.f - 1.f; gy = fminf(fmaxf(gy, -1.f), 1.f);
        float ix = ((gx + 1.f) * (float)W_ - 1.f) * 0.5f;
        float iy = ((gy + 1.f) * (float)H_ - 1.f) * 0.5f;
        float x0f = floorf(ix), y0f = floorf(iy);
        float wx = ix - x0f, wy = iy - y0f;
        int x0 = (int)x0f, y0 = (int)y0f;
        float acc = 0.f;
        #pragma unroll
        for (int cy = 0; cy < 2; cy++) {
            #pragma unroll
            for (int cx = 0; cx < 2; cx++) {
                int yc = y0 + cy, xc = x0 + cx;
                float wgt = (cx ? wx : 1.f - wx) * (cy ? wy : 1.f - wy);
                if (xc >= 0 && xc < W_ && yc >= 0 && yc < H_) {
                    acc = fmaf(wgt,
                               g_imgT[(((size_t)(b * H_ + yc)) * W_ + xc) * C2D + j],
                               acc);
                }
            }
        }
        g_ifeat[(size_t)row * C2D + j] = acc;
    }
}

// ---------------- K5: attention scalar ----------------
// 256 threads: j = t>>1, h = t&1 (128 floats each). Atomic-free reduction.
__global__ __launch_bounds__(256) void k_att(const float* __restrict__ aw1,
                                             const float* __restrict__ ab1,
                                             const float* __restrict__ aw2,
                                             const float* __restrict__ ab2,
                                             int N) {
    int t = threadIdx.x;
    int j = t >> 1, h = t & 1;
    int wid = t >> 5, lane = t & 31;
    ull w[64];
    const ulonglong2* wp = reinterpret_cast<const ulonglong2*>(aw1 + (size_t)j * 256 + h * 128);
    #pragma unroll
    for (int k = 0; k < 32; k++) { ulonglong2 v = wp[k]; w[2*k] = v.x; w[2*k+1] = v.y; }
    float bj  = __ldg(ab1 + j);
    float w2j = (h == 0) ? __ldg(aw2 + j) : 0.f;
    float b2  = __ldg(ab2);
    __shared__ __align__(16) float sc[8][256];
    __shared__ float spart[8][8];   // [row][warp]
    int row0 = blockIdx.x * ROWS_BLK;
    int ntile = (N - row0 + 7) / 8; if (ntile > ROWS_BLK / 8) ntile = ROWS_BLK / 8;

    // loader: 2 float4 per thread (8 rows x 256 cols)
    int lr = t >> 6, lc = (t & 63) * 4;
    float4 pf0 = make_float4(0.f,0.f,0.f,0.f), pf1 = pf0;
    {
        int r0 = row0 + lr, r1 = row0 + lr + 4;
        if (r0 < N)
            pf0 = (lc < 128)
                ? *reinterpret_cast<const float4*>(g_vfeat + (size_t)r0 * 128 + lc)
                : *reinterpret_cast<const float4*>(g_ifeat + (size_t)r0 * 128 + lc - 128);
        if (r1 < N)
            pf1 = (lc < 128)
                ? *reinterpret_cast<const float4*>(g_vfeat + (size_t)r1 * 128 + lc)
                : *reinterpret_cast<const float4*>(g_ifeat + (size_t)r1 * 128 + lc - 128);
    }

    for (int tl = 0; tl < ntile; tl++) {
        int base = row0 + tl * 8;
        *reinterpret_cast<float4*>(&sc[lr][lc])     = pf0;
        *reinterpret_cast<float4*>(&sc[lr + 4][lc]) = pf1;
        __syncthreads();
        if (tl + 1 < ntile) {
            int nb = base + 8;
            pf0 = make_float4(0.f,0.f,0.f,0.f); pf1 = pf0;
            int r0 = nb + lr, r1 = nb + lr + 4;
            if (r0 < N)
                pf0 = (lc < 128)
                    ? *reinterpret_cast<const float4*>(g_vfeat + (size_t)r0 * 128 + lc)
                    : *reinterpret_cast<const float4*>(g_ifeat + (size_t)r0 * 128 + lc - 128);
            if (r1 < N)
                pf1 = (lc < 128)
                    ? *reinterpret_cast<const float4*>(g_vfeat + (size_t)r1 * 128 + lc)
                    : *reinterpret_cast<const float4*>(g_ifeat + (size_t)r1 * 128 + lc - 128);
        }
        #pragma unroll
        for (int r = 0; r < 8; r++) {
            ull a0 = 0, a1 = 0, a2 = 0, a3 = 0;
            const ulonglong2* xp = reinterpret_cast<const ulonglong2*>(&sc[r][0] + h * 128);
            #pragma unroll
            for (int k = 0; k < 16; k++) {
                ulonglong2 x0 = xp[2*k], x1 = xp[2*k+1];
                fma2(a0, w[4*k],   x0.x);
                fma2(a1, w[4*k+1], x0.y);
                fma2(a2, w[4*k+2], x1.x);
                fma2(a3, w[4*k+3], x1.y);
            }
            float s = (upsum(a0) + upsum(a1)) + (upsum(a2) + upsum(a3));
            s += __shfl_xor_sync(0xffffffffu, s, 1);        // combine halves
            float v = fmaxf(s + bj, 0.f) * w2j;              // nonzero only h==0
            #pragma unroll
            for (int o = 16; o > 1; o >>= 1) v += __shfl_xor_sync(0xffffffffu, v, o);
            v += __shfl_xor_sync(0xffffffffu, v, 1);
            if (lane == 0) spart[r][wid] = v;                // plain STS, no atomics
        }
        __syncthreads();
        if (t < 8 && base + t < N) {
            float s = b2;
            #pragma unroll
            for (int i = 0; i < 8; i++) s += spart[t][i];
            g_att[base + t] = 1.f / (1.f + expf(-s));
        }
        __syncthreads();
    }
}

// ---------------- K6: fused GEMM -> out_pre, bnf stats ----------------
// 256 threads: j = t>>1, h = t&1. Register prefetch.
__global__ __launch_bounds__(256) void k_fuse(const float* __restrict__ fw,
                                              const float* __restrict__ fb,
                                              float* __restrict__ out,
                                              int N) {
    int t = threadIdx.x;
    int j = t >> 1, h = t & 1;
    ull w[64];
    const ulonglong2* wp = reinterpret_cast<const ulonglong2*>(fw + (size_t)j * 256 + h * 128);
    #pragma unroll
    for (int k = 0; k < 32; k++) { ulonglong2 v = wp[k]; w[2*k] = v.x; w[2*k+1] = v.y; }
    float bias = __ldg(fb + j);
    __shared__ __align__(16) float sc[8][256];
    __shared__ float sa[8];
    float ssum = 0.f, ssq = 0.f;
    int row0 = blockIdx.x * ROWS_BLK;
    int ntile = (N - row0 + 7) / 8; if (ntile > ROWS_BLK / 8) ntile = ROWS_BLK / 8;

    int lr = t >> 6, lc = (t & 63) * 4;
    float4 pf0 = make_float4(0.f,0.f,0.f,0.f), pf1 = pf0;
    {
        int r0 = row0 + lr, r1 = row0 + lr + 4;
        if (r0 < N)
            pf0 = (lc < 128)
                ? *reinterpret_cast<const float4*>(g_vfeat + (size_t)r0 * 128 + lc)
                : *reinterpret_cast<const float4*>(g_ifeat + (size_t)r0 * 128 + lc - 128);
        if (r1 < N)
            pf1 = (lc < 128)
                ? *reinterpret_cast<const float4*>(g_vfeat + (size_t)r1 * 128 + lc)
                : *reinterpret_cast<const float4*>(g_ifeat + (size_t)r1 * 128 + lc - 128);
    }

    for (int tl = 0; tl < ntile; tl++) {
        int base = row0 + tl * 8;
        {   // scale by a / (1-a) at store time
            float a0 = (base + lr     < N) ? g_att[base + lr]     : 0.f;
            float a1 = (base + lr + 4 < N) ? g_att[base + lr + 4] : 0.f;
            float m0 = (lc < 128) ? a0 : 1.f - a0;
            float m1 = (lc < 128) ? a1 : 1.f - a1;
            float4 v = pf0;
            v.x *= m0; v.y *= m0; v.z *= m0; v.w *= m0;
            *reinterpret_cast<float4*>(&sc[lr][lc]) = v;
            v = pf1;
            v.x *= m1; v.y *= m1; v.z *= m1; v.w *= m1;
            *reinterpret_cast<float4*>(&sc[lr + 4][lc]) = v;
        }
        if (t < 8) sa[t] = (base + t < N) ? g_att[base + t] : 0.f;
        __syncthreads();
        if (tl + 1 < ntile) {
            int nb = base + 8;
            pf0 = make_float4(0.f,0.f,0.f,0.f); pf1 = pf0;
            int r0 = nb + lr, r1 = nb + lr + 4;
            if (r0 < N)
                pf0 = (lc < 128)
                    ? *reinterpret_cast<const float4*>(g_vfeat + (size_t)r0 * 128 + lc)
                    : *reinterpret_cast<const float4*>(g_ifeat + (size_t)r0 * 128 + lc - 128);
            if (r1 < N)
                pf1 = (lc < 128)
                    ? *reinterpret_cast<const float4*>(g_vfeat + (size_t)r1 * 128 + lc)
                    : *reinterpret_cast<const float4*>(g_ifeat + (size_t)r1 * 128 + lc - 128);
        }
        #pragma unroll
        for (int r = 0; r < 8; r++) {
            if (base + r < N) {
                ull a0 = 0, a1 = 0, a2 = 0, a3 = 0;
                const ulonglong2* xp = reinterpret_cast<const ulonglong2*>(&sc[r][0] + h * 128);
                #pragma unroll
                for (int k = 0; k < 16; k++) {
                    ulonglong2 x0 = xp[2*k], x1 = xp[2*k+1];
                    fma2(a0, w[4*k],   x0.x);
                    fma2(a1, w[4*k+1], x0.y);
                    fma2(a2, w[4*k+2], x1.x);
                    fma2(a3, w[4*k+3], x1.y);
                }
                float acc = (upsum(a0) + upsum(a1)) + (upsum(a2) + upsum(a3));
                acc += __shfl_xor_sync(0xffffffffu, acc, 1);
                if (h == 0) {
                    float o = acc + bias;
                    out[(size_t)(base + r) * 128 + j] = o;
                    ssum += o; ssq += o * o;
                }
            }
        }
        __syncthreads();
    }
    if (h == 0) {
        atomicAdd(&g_stats[256 + j], ssum);
        atomicAdd(&g_stats[384 + j], ssq);
    }
}

// ---------------- K8: in-place final bn + relu ----------------
__global__ void k_bnrelu(float* __restrict__ out, long total4) {
    long i = (long)blockIdx.x * blockDim.x + threadIdx.x;
    if (i < total4) {
        int cb = (int)((i & 31) * 4);
        float4 v = reinterpret_cast<float4*>(out)[i];
        v.x = fmaxf(fmaf(v.x, g_bnp[256 + cb],     g_bnp[384 + cb]),     0.f);
        v.y = fmaxf(fmaf(v.y, g_bnp[256 + cb + 1], g_bnp[384 + cb + 1]), 0.f);
        v.z = fmaxf(fmaf(v.z, g_bnp[256 + cb + 2], g_bnp[384 + cb + 2]), 0.f);
        v.w = fmaxf(fmaf(v.w, g_bnp[256 + cb + 3], g_bnp[384 + cb + 3]), 0.f);
        reinterpret_cast<float4*>(out)[i] = v;
    }
}

// ---------------- launch ----------------
extern "C" void kernel_launch(void* const* d_in, const int* in_sizes, int n_in,
                              void* d_out, int out_size) {
    const float* vf     = (const float*)d_in[0];
    const int*   coords = (const int*)  d_in[1];
    const float* img    = (const float*)d_in[2];
    const float* P2     = (const float*)d_in[3];
    const float* vt_w1  = (const float*)d_in[4];
    const float* vt_b1  = (const float*)d_in[5];
    const float* bn1_g  = (const float*)d_in[6];
    const float* bn1_b  = (const float*)d_in[7];
    const float* vt_w2  = (const float*)d_in[8];
    const float* vt_b2  = (const float*)d_in[9];
    const float* att_w1 = (const float*)d_in[10];
    const float* att_b1 = (const float*)d_in[11];
    const float* att_w2 = (const float*)d_in[12];
    const float* att_b2 = (const float*)d_in[13];
    const float* fus_w  = (const float*)d_in[14];
    const float* fus_b  = (const float*)d_in[15];
    const float* bnf_g  = (const float*)d_in[16];
    const float* bnf_b  = (const float*)d_in[17];

    int N = in_sizes[1] / 4;
    float* out = (float*)d_out;
    int nblk = (N + ROWS_BLK - 1) / ROWS_BLK;

    k_transpose<<<dim3((W_ + 31) / 32, C2D / 32, B_ * H_), dim3(32, 8)>>>(img);
    k_zero<<<1, 512>>>();
    k_gemm1<<<nblk, 128>>>(vf, vt_w1, vt_b1, N);
    k_fin<<<1, 128>>>(0, bn1_g, bn1_b, N);
    k_gemm2<<<nblk, 128>>>(vt_w2, vt_b2, N);
    k_sample<<<(N + 63) / 64, 256>>>(coords, P2, N);
    k_att<<<nblk, 256>>>(att_w1, att_b1, att_w2, att_b2, N);
    k_fuse<<<nblk, 256>>>(fus_w, fus_b, out, N);
    k_fin<<<1, 128>>>(1, bnf_g, bnf_b, N);
    long total4 = (long)N * 32;
    k_bnrelu<<<(unsigned)((total4 + 255) / 256), 256>>>(out, total4);
}

// round 9
// speedup vs baseline: 5.9583x; 2.0587x over previous
#include <cuda_runtime.h>
#include <math.h>
#include <stdint.h>

// ---------------- problem constants ----------------
#define NMAX 200000
#define B_   4
#define C2D  128
#define H_   96
#define W_   312
#define MID  128
#define C3D  64
#define BM   128
#define KC   16

// ---------------- scratch ----------------
__device__ __align__(16) float g_imgT[(size_t)B_ * H_ * W_ * C2D];
__device__ __align__(16) float g_hpre[(size_t)NMAX * MID];
__device__ __align__(16) float g_vfeat[(size_t)NMAX * MID];
__device__ __align__(16) float g_ifeat[(size_t)NMAX * C2D];
__device__ float g_att[NMAX];
__device__ float g_stats[512];
__device__ float g_bnp[512];

__global__ void k_zero() {
    if (threadIdx.x < 512) g_stats[threadIdx.x] = 0.f;
}

// ---------------- K0: image transpose [B,C,H,W] -> [B,H,W,C] ----------------
__global__ void k_transpose(const float* __restrict__ img) {
    __shared__ float tile[32][33];
    int bh = blockIdx.z;
    int b  = bh / H_;
    int hh = bh % H_;
    int w0 = blockIdx.x * 32;
    int c0 = blockIdx.y * 32;
    int tx = threadIdx.x, ty = threadIdx.y;
    #pragma unroll
    for (int i = 0; i < 32; i += 8) {
        int c = c0 + ty + i;
        int w = w0 + tx;
        float v = 0.f;
        if (w < W_) v = img[((size_t)(b * C2D + c) * H_ + hh) * W_ + w];
        tile[ty + i][tx] = v;
    }
    __syncthreads();
    #pragma unroll
    for (int i = 0; i < 32; i += 8) {
        int w = w0 + ty + i;
        int c = c0 + tx;
        if (w < W_)
            g_imgT[((size_t)bh * W_ + w) * C2D + c] = tile[tx][ty + i];
    }
}

// ---------------- shared GEMM pieces ----------------
// load 128 rows x KC cols of row-major src -> transposed smem sT[k][row]
__device__ __forceinline__ void load_T(float (*sT)[BM], const float* __restrict__ src,
                                       int ld, int base, int N, int kofs, int t) {
    #pragma unroll
    for (int i = 0; i < 2; i++) {
        int idx = i * 256 + t;          // 0..511
        int r = idx >> 2, k0 = (idx & 3) * 4;
        float4 v = make_float4(0.f, 0.f, 0.f, 0.f);
        if (base + r < N)
            v = *reinterpret_cast<const float4*>(src + (size_t)(base + r) * ld + kofs + k0);
        sT[k0][r] = v.x; sT[k0 + 1][r] = v.y; sT[k0 + 2][r] = v.z; sT[k0 + 3][r] = v.w;
    }
}

// scalar FFMA core: 8x8 per-thread tile
__device__ __forceinline__ void gemm_chunk(const float (*sAT)[BM], const float (*sBT)[BM],
                                           float acc[8][8], int tr8, int tc8) {
    #pragma unroll
    for (int k = 0; k < KC; k++) {
        float4 a0 = *reinterpret_cast<const float4*>(&sAT[k][tr8]);
        float4 a1 = *reinterpret_cast<const float4*>(&sAT[k][tr8 + 4]);
        float4 b0 = *reinterpret_cast<const float4*>(&sBT[k][tc8]);
        float4 b1 = *reinterpret_cast<const float4*>(&sBT[k][tc8 + 4]);
        float av[8] = {a0.x, a0.y, a0.z, a0.w, a1.x, a1.y, a1.z, a1.w};
        float bv[8] = {b0.x, b0.y, b0.z, b0.w, b1.x, b1.y, b1.z, b1.w};
        #pragma unroll
        for (int r = 0; r < 8; r++)
            #pragma unroll
            for (int c = 0; c < 8; c++)
                acc[r][c] = fmaf(av[r], bv[c], acc[r][c]);
    }
}

// store 8x8 tile (+bias) to row-major dst[*,128]
__device__ __forceinline__ void store_tile(float* __restrict__ dst, const float acc[8][8],
                                           const float* __restrict__ bias,
                                           int base, int N, int tr8, int tc8) {
    float4 bb0 = *reinterpret_cast<const float4*>(bias + tc8);
    float4 bb1 = *reinterpret_cast<const float4*>(bias + tc8 + 4);
    #pragma unroll
    for (int r = 0; r < 8; r++) {
        int row = base + tr8 + r;
        if (row < N) {
            float4 f0 = make_float4(acc[r][0] + bb0.x, acc[r][1] + bb0.y,
                                    acc[r][2] + bb0.z, acc[r][3] + bb0.w);
            float4 f1 = make_float4(acc[r][4] + bb1.x, acc[r][5] + bb1.y,
                                    acc[r][6] + bb1.z, acc[r][7] + bb1.w);
            *reinterpret_cast<float4*>(dst + (size_t)row * 128 + tc8) = f0;
            *reinterpret_cast<float4*>(dst + (size_t)row * 128 + tc8 + 4) = f1;
        }
    }
}

#define GEMM_PROLOG() \
    int t = threadIdx.x; \
    int tc8 = (t & 15) * 8, tr8 = (t >> 4) * 8; \
    int base = blockIdx.x * BM; \
    float acc[8][8]; \
    _Pragma("unroll") \
    for (int r = 0; r < 8; r++) \
        _Pragma("unroll") \
        for (int c = 0; c < 8; c++) acc[r][c] = 0.f;

// ---------------- K1: hpre = vf @ w1^T + b1 ----------------
__global__ __launch_bounds__(256, 2) void k_gemm1(const float* __restrict__ vf,
                                                  const float* __restrict__ w1,
                                                  const float* __restrict__ b1, int N) {
    __shared__ __align__(16) float sAT[KC][BM];
    __shared__ __align__(16) float sBT[KC][BM];
    GEMM_PROLOG();
    for (int ck = 0; ck < C3D; ck += KC) {
        load_T(sAT, vf, C3D, base, N, ck, t);
        load_T(sBT, w1, C3D, 0, 1 << 30, ck, t);
        __syncthreads();
        gemm_chunk(sAT, sBT, acc, tr8, tc8);
        __syncthreads();
    }
    store_tile(g_hpre, acc, b1, base, N, tr8, tc8);
}

// ---------------- stats over a [N,128] array ----------------
// NOTE: src==nullptr means "use g_hpre" — the __device__ symbol must be
// resolved in DEVICE code; passing it from the host launcher yields the
// host shadow address (silently readable via ATS on GB300 => garbage stats).
__global__ __launch_bounds__(128) void k_stats(const float* src, int off,
                                               int N, int rpb) {
    if (src == nullptr) src = g_hpre;
    __shared__ float ss[128], sq[128];
    int t = threadIdx.x;
    ss[t] = 0.f; sq[t] = 0.f;
    __syncthreads();
    int q4 = (t & 31) * 4, rg = t >> 5;
    long r0 = (long)blockIdx.x * rpb;
    long r1 = r0 + rpb; if (r1 > N) r1 = N;
    float s0=0,s1=0,s2=0,s3=0, p0=0,p1=0,p2=0,p3=0;
    for (long r = r0 + rg; r < r1; r += 4) {
        float4 v = *reinterpret_cast<const float4*>(src + r * 128 + q4);
        s0 += v.x; s1 += v.y; s2 += v.z; s3 += v.w;
        p0 += v.x * v.x; p1 += v.y * v.y; p2 += v.z * v.z; p3 += v.w * v.w;
    }
    atomicAdd(&ss[q4], s0);     atomicAdd(&ss[q4 + 1], s1);
    atomicAdd(&ss[q4 + 2], s2); atomicAdd(&ss[q4 + 3], s3);
    atomicAdd(&sq[q4], p0);     atomicAdd(&sq[q4 + 1], p1);
    atomicAdd(&sq[q4 + 2], p2); atomicAdd(&sq[q4 + 3], p3);
    __syncthreads();
    atomicAdd(&g_stats[off + t], ss[t]);
    atomicAdd(&g_stats[off + 128 + t], sq[t]);
}

// ---------------- finalize bn stats ----------------
__global__ void k_fin(int which, const float* __restrict__ g,
                      const float* __restrict__ b, int N) {
    int j = threadIdx.x;
    int o = which * 256;
    float invN = 1.f / (float)N;
    float m   = g_stats[o + j] * invN;
    float msq = g_stats[o + 128 + j] * invN;
    float var = msq - m * m;
    float s = __ldg(g + j) * rsqrtf(var + 1e-5f);
    g_bnp[o + j] = s;
    g_bnp[o + 128 + j] = __ldg(b + j) - m * s;
}

// ---------------- K3: vfeat = relu(bn(hpre)) @ w2^T + b2 ----------------
__global__ __launch_bounds__(256, 2) void k_gemm2(const float* __restrict__ w2,
                                                  const float* __restrict__ b2, int N) {
    __shared__ __align__(16) float sAT[KC][BM];
    __shared__ __align__(16) float sBT[KC][BM];
    __shared__ float sS[MID], sH[MID];
    GEMM_PROLOG();
    if (t < 128) { sS[t] = g_bnp[t]; sH[t] = g_bnp[128 + t]; }
    __syncthreads();
    for (int ck = 0; ck < MID; ck += KC) {
        #pragma unroll
        for (int i = 0; i < 2; i++) {   // A loader with bn+relu
            int idx = i * 256 + t;
            int r = idx >> 2, k0 = (idx & 3) * 4;
            float4 v = make_float4(0.f, 0.f, 0.f, 0.f);
            if (base + r < N)
                v = *reinterpret_cast<const float4*>(g_hpre + (size_t)(base + r) * MID + ck + k0);
            int gk = ck + k0;
            v.x = fmaxf(fmaf(v.x, sS[gk],     sH[gk]),     0.f);
            v.y = fmaxf(fmaf(v.y, sS[gk + 1], sH[gk + 1]), 0.f);
            v.z = fmaxf(fmaf(v.z, sS[gk + 2], sH[gk + 2]), 0.f);
            v.w = fmaxf(fmaf(v.w, sS[gk + 3], sH[gk + 3]), 0.f);
            sAT[k0][r] = v.x; sAT[k0+1][r] = v.y; sAT[k0+2][r] = v.z; sAT[k0+3][r] = v.w;
        }
        load_T(sBT, w2, MID, 0, 1 << 30, ck, t);
        __syncthreads();
        gemm_chunk(sAT, sBT, acc, tr8, tc8);
        __syncthreads();
    }
    store_tile(g_vfeat, acc, b2, base, N, tr8, tc8);
}

// ---------------- K4: projection + bilinear gather -> ifeat ----------------
__global__ __launch_bounds__(256) void k_sample(const int* __restrict__ coords,
                                                const float* __restrict__ P2, int N) {
    int j  = threadIdx.x & 127;
    int rr = threadIdx.x >> 7;
    int row0 = blockIdx.x * 64;
    for (int r = rr; r < 64; r += 2) {
        int row = row0 + r;
        if (row >= N) break;
        int4 c4 = __ldg(reinterpret_cast<const int4*>(coords + (size_t)row * 4));
        int b = c4.x;
        float p0 = (float)c4.y * 0.05f;
        float p1 = (float)c4.z * 0.05f - 40.f;
        float p2 = (float)c4.w * 0.1f  - 3.f;
        const float* P = P2 + b * 12;
        float cam0 = __ldg(P+0)*p0 + __ldg(P+1)*p1 + __ldg(P+2)*p2  + __ldg(P+3);
        float cam1 = __ldg(P+4)*p0 + __ldg(P+5)*p1 + __ldg(P+6)*p2  + __ldg(P+7);
        float cam2 = __ldg(P+8)*p0 + __ldg(P+9)*p1 + __ldg(P+10)*p2 + __ldg(P+11);
        float d = cam2 + 1e-8f;
        float u = cam0 / d;
        float v = cam1 / d;
        float gx = u / (float)W_ * 2.f - 1.f; gx = fminf(fmaxf(gx, -1.f), 1.f);
        float gy = v / (float)H_ * 2.f - 1.f; gy = fminf(fmaxf(gy, -1.f), 1.f);
        float ix = ((gx + 1.f) * (float)W_ - 1.f) * 0.5f;
        float iy = ((gy + 1.f) * (float)H_ - 1.f) * 0.5f;
        float x0f = floorf(ix), y0f = floorf(iy);
        float wx = ix - x0f, wy = iy - y0f;
        int x0 = (int)x0f, y0 = (int)y0f;
        float acc = 0.f;
        #pragma unroll
        for (int cy = 0; cy < 2; cy++) {
            #pragma unroll
            for (int cx = 0; cx < 2; cx++) {
                int yc = y0 + cy, xc = x0 + cx;
                float wgt = (cx ? wx : 1.f - wx) * (cy ? wy : 1.f - wy);
                if (xc >= 0 && xc < W_ && yc >= 0 && yc < H_) {
                    acc = fmaf(wgt,
                               g_imgT[(((size_t)(b * H_ + yc)) * W_ + xc) * C2D + j],
                               acc);
                }
            }
        }
        g_ifeat[(size_t)row * C2D + j] = acc;
    }
}

// ---------------- K5: attention scalar (GEMM + 128->1 + sigmoid) ----------------
__global__ __launch_bounds__(256, 2) void k_att(const float* __restrict__ aw1,
                                                const float* __restrict__ ab1,
                                                const float* __restrict__ aw2,
                                                const float* __restrict__ ab2, int N) {
    __shared__ __align__(16) float sAT[KC][BM];
    __shared__ __align__(16) float sBT[KC][BM];
    __shared__ float sred[BM][17];
    GEMM_PROLOG();
    for (int ck = 0; ck < 256; ck += KC) {
        const float* src = (ck < 128) ? g_vfeat : g_ifeat;
        int ko = (ck < 128) ? ck : ck - 128;
        load_T(sAT, src, 128, base, N, ko, t);
        load_T(sBT, aw1, 256, 0, 1 << 30, ck, t);
        __syncthreads();
        gemm_chunk(sAT, sBT, acc, tr8, tc8);
        __syncthreads();
    }
    float4 bb0 = *reinterpret_cast<const float4*>(ab1 + tc8);
    float4 bb1 = *reinterpret_cast<const float4*>(ab1 + tc8 + 4);
    float bv[8] = {bb0.x, bb0.y, bb0.z, bb0.w, bb1.x, bb1.y, bb1.z, bb1.w};
    float4 ww0 = *reinterpret_cast<const float4*>(aw2 + tc8);
    float4 ww1 = *reinterpret_cast<const float4*>(aw2 + tc8 + 4);
    float wv[8] = {ww0.x, ww0.y, ww0.z, ww0.w, ww1.x, ww1.y, ww1.z, ww1.w};
    #pragma unroll
    for (int r = 0; r < 8; r++) {
        float s = 0.f;
        #pragma unroll
        for (int c = 0; c < 8; c++)
            s += fmaxf(acc[r][c] + bv[c], 0.f) * wv[c];
        sred[tr8 + r][t & 15] = s;
    }
    __syncthreads();
    if (t < 128 && base + t < N) {
        float s = __ldg(ab2);
        #pragma unroll
        for (int i = 0; i < 16; i++) s += sred[t][i];
        g_att[base + t] = 1.f / (1.f + expf(-s));
    }
}

// ---------------- K6: fused GEMM -> out_pre ----------------
__global__ __launch_bounds__(256, 2) void k_fuse(const float* __restrict__ fw,
                                                 const float* __restrict__ fb,
                                                 float* __restrict__ out, int N) {
    __shared__ __align__(16) float sAT[KC][BM];
    __shared__ __align__(16) float sBT[KC][BM];
    __shared__ float sa[BM];
    GEMM_PROLOG();
    if (t < 128) sa[t] = (base + t < N) ? g_att[base + t] : 0.f;
    __syncthreads();
    for (int ck = 0; ck < 256; ck += KC) {
        bool isv = (ck < 128);
        const float* src = isv ? g_vfeat : g_ifeat;
        int ko = isv ? ck : ck - 128;
        #pragma unroll
        for (int i = 0; i < 2; i++) {   // A loader with attention scaling
            int idx = i * 256 + t;
            int r = idx >> 2, k0 = (idx & 3) * 4;
            float4 v = make_float4(0.f, 0.f, 0.f, 0.f);
            float m = 0.f;
            if (base + r < N) {
                v = *reinterpret_cast<const float4*>(src + (size_t)(base + r) * 128 + ko + k0);
                m = isv ? sa[r] : 1.f - sa[r];
            }
            sAT[k0][r] = v.x * m; sAT[k0+1][r] = v.y * m;
            sAT[k0+2][r] = v.z * m; sAT[k0+3][r] = v.w * m;
        }
        load_T(sBT, fw, 256, 0, 1 << 30, ck, t);
        __syncthreads();
        gemm_chunk(sAT, sBT, acc, tr8, tc8);
        __syncthreads();
    }
    store_tile(out, acc, fb, base, N, tr8, tc8);
}

// ---------------- K8: in-place final bn + relu ----------------
__global__ void k_bnrelu(float* __restrict__ out, long total4) {
    long i = (long)blockIdx.x * blockDim.x + threadIdx.x;
    if (i < total4) {
        int cb = (int)((i & 31) * 4);
        float4 v = reinterpret_cast<float4*>(out)[i];
        v.x = fmaxf(fmaf(v.x, g_bnp[256 + cb],     g_bnp[384 + cb]),     0.f);
        v.y = fmaxf(fmaf(v.y, g_bnp[256 + cb + 1], g_bnp[384 + cb + 1]), 0.f);
        v.z = fmaxf(fmaf(v.z, g_bnp[256 + cb + 2], g_bnp[384 + cb + 2]), 0.f);
        v.w = fmaxf(fmaf(v.w, g_bnp[256 + cb + 3], g_bnp[384 + cb + 3]), 0.f);
        reinterpret_cast<float4*>(out)[i] = v;
    }
}

// ---------------- launch ----------------
extern "C" void kernel_launch(void* const* d_in, const int* in_sizes, int n_in,
                              void* d_out, int out_size) {
    const float* vf     = (const float*)d_in[0];
    const int*   coords = (const int*)  d_in[1];
    const float* img    = (const float*)d_in[2];
    const float* P2     = (const float*)d_in[3];
    const float* vt_w1  = (const float*)d_in[4];
    const float* vt_b1  = (const float*)d_in[5];
    const float* bn1_g  = (const float*)d_in[6];
    const float* bn1_b  = (const float*)d_in[7];
    const float* vt_w2  = (const float*)d_in[8];
    const float* vt_b2  = (const float*)d_in[9];
    const float* att_w1 = (const float*)d_in[10];
    const float* att_b1 = (const float*)d_in[11];
    const float* att_w2 = (const float*)d_in[12];
    const float* att_b2 = (const float*)d_in[13];
    const float* fus_w  = (const float*)d_in[14];
    const float* fus_b  = (const float*)d_in[15];
    const float* bnf_g  = (const float*)d_in[16];
    const float* bnf_b  = (const float*)d_in[17];

    int N = in_sizes[1] / 4;
    float* out = (float*)d_out;
    int nblk = (N + BM - 1) / BM;
    int sblk = 512, rpb = (N + sblk - 1) / sblk;

    k_transpose<<<dim3((W_ + 31) / 32, C2D / 32, B_ * H_), dim3(32, 8)>>>(img);
    k_zero<<<1, 512>>>();
    k_gemm1<<<nblk, 256>>>(vf, vt_w1, vt_b1, N);
    k_stats<<<sblk, 128>>>(nullptr, 0, N, rpb);   // nullptr => g_hpre (device-side resolve)
    k_fin<<<1, 128>>>(0, bn1_g, bn1_b, N);
    k_gemm2<<<nblk, 256>>>(vt_w2, vt_b2, N);
    k_sample<<<(N + 63) / 64, 256>>>(coords, P2, N);
    k_att<<<nblk, 256>>>(att_w1, att_b1, att_w2, att_b2, N);
    k_fuse<<<nblk, 256>>>(fus_w, fus_b, out, N);
    k_stats<<<sblk, 128>>>(out, 256, N, rpb);
    k_fin<<<1, 128>>>(1, bnf_g, bnf_b, N);
    long total4 = (long)N * 32;
    k_bnrelu<<<(unsigned)((total4 + 255) / 256), 256>>>(out, total4);
}

// round 10
// speedup vs baseline: 6.5268x; 1.0954x over previous
#include <cuda_runtime.h>
#include <math.h>
#include <stdint.h>

// ---------------- problem constants ----------------
#define NMAX 200000
#define B_   4
#define C2D  128
#define H_   96
#define W_   312
#define MID  128
#define C3D  64
#define BM   128
#define KC   16

typedef unsigned long long ull;

__device__ __forceinline__ void fma2(ull& d, ull a, ull b) {
    asm("fma.rn.f32x2 %0, %1, %2, %0;" : "+l"(d) : "l"(a), "l"(b));
}
__device__ __forceinline__ ull dup2(float b) {
    ull r; asm("mov.b64 %0, {%1, %1};" : "=l"(r) : "f"(b)); return r;
}
__device__ __forceinline__ float ulo(ull a) { return __uint_as_float((unsigned)a); }
__device__ __forceinline__ float uhi(ull a) { return __uint_as_float((unsigned)(a >> 32)); }

// ---------------- scratch ----------------
__device__ __align__(16) float g_imgT[(size_t)B_ * H_ * W_ * C2D];
__device__ __align__(16) float g_hpre[(size_t)NMAX * MID];
__device__ __align__(16) float g_vfeat[(size_t)NMAX * MID];
__device__ __align__(16) float g_ifeat[(size_t)NMAX * C2D];
__device__ float g_att[NMAX];
__device__ float g_stats[512];
__device__ float g_bnp[512];

__global__ void k_zero() {
    if (threadIdx.x < 512) g_stats[threadIdx.x] = 0.f;
}

// ---------------- K0: image transpose [B,C,H,W] -> [B,H,W,C] ----------------
__global__ void k_transpose(const float* __restrict__ img) {
    __shared__ float tile[32][33];
    int bh = blockIdx.z;
    int b  = bh / H_;
    int hh = bh % H_;
    int w0 = blockIdx.x * 32;
    int c0 = blockIdx.y * 32;
    int tx = threadIdx.x, ty = threadIdx.y;
    #pragma unroll
    for (int i = 0; i < 32; i += 8) {
        int c = c0 + ty + i;
        int w = w0 + tx;
        float v = 0.f;
        if (w < W_) v = img[((size_t)(b * C2D + c) * H_ + hh) * W_ + w];
        tile[ty + i][tx] = v;
    }
    __syncthreads();
    #pragma unroll
    for (int i = 0; i < 32; i += 8) {
        int w = w0 + ty + i;
        int c = c0 + tx;
        if (w < W_)
            g_imgT[((size_t)bh * W_ + w) * C2D + c] = tile[tx][ty + i];
    }
}

// ---------------- shared GEMM pieces ----------------
// load 128 rows x KC cols of row-major src -> transposed smem sT[k][row]
__device__ __forceinline__ void load_T(float (*sT)[BM], const float* __restrict__ src,
                                       int ld, int base, int N, int kofs, int t) {
    #pragma unroll
    for (int i = 0; i < 2; i++) {
        int idx = i * 256 + t;          // 0..511
        int r = idx >> 2, k0 = (idx & 3) * 4;
        float4 v = make_float4(0.f, 0.f, 0.f, 0.f);
        if (base + r < N)
            v = *reinterpret_cast<const float4*>(src + (size_t)(base + r) * ld + kofs + k0);
        sT[k0][r] = v.x; sT[k0 + 1][r] = v.y; sT[k0 + 2][r] = v.z; sT[k0 + 3][r] = v.w;
    }
}

// f32x2 core: A row-pairs from smem, B scalars dup'd in-register.
// acc[c][p] holds rows (tr8+2p, tr8+2p+1) for output column tc8+c.
__device__ __forceinline__ void gemm_chunk(const float (*sAT)[BM], const float (*sBT)[BM],
                                           ull acc[8][4], int tr8, int tc8) {
    #pragma unroll
    for (int k = 0; k < KC; k++) {
        ulonglong2 aA = *reinterpret_cast<const ulonglong2*>(&sAT[k][tr8]);
        ulonglong2 aB = *reinterpret_cast<const ulonglong2*>(&sAT[k][tr8 + 4]);
        float4 b0 = *reinterpret_cast<const float4*>(&sBT[k][tc8]);
        float4 b1 = *reinterpret_cast<const float4*>(&sBT[k][tc8 + 4]);
        float bs[8] = {b0.x, b0.y, b0.z, b0.w, b1.x, b1.y, b1.z, b1.w};
        #pragma unroll
        for (int c = 0; c < 8; c++) {
            ull bd = dup2(bs[c]);
            fma2(acc[c][0], aA.x, bd);
            fma2(acc[c][1], aA.y, bd);
            fma2(acc[c][2], aB.x, bd);
            fma2(acc[c][3], aB.y, bd);
        }
    }
}

// store 8x8 tile (+bias) to row-major dst[*,128]; lo lane = even row of pair
__device__ __forceinline__ void store_tile(float* __restrict__ dst, const ull acc[8][4],
                                           const float* __restrict__ bias,
                                           int base, int N, int tr8, int tc8) {
    float4 bb0 = *reinterpret_cast<const float4*>(bias + tc8);
    float4 bb1 = *reinterpret_cast<const float4*>(bias + tc8 + 4);
    float bv[8] = {bb0.x, bb0.y, bb0.z, bb0.w, bb1.x, bb1.y, bb1.z, bb1.w};
    #pragma unroll
    for (int p = 0; p < 4; p++) {
        int r0 = base + tr8 + 2 * p;
        if (r0 < N) {
            float4 f0 = make_float4(ulo(acc[0][p]) + bv[0], ulo(acc[1][p]) + bv[1],
                                    ulo(acc[2][p]) + bv[2], ulo(acc[3][p]) + bv[3]);
            float4 f1 = make_float4(ulo(acc[4][p]) + bv[4], ulo(acc[5][p]) + bv[5],
                                    ulo(acc[6][p]) + bv[6], ulo(acc[7][p]) + bv[7]);
            *reinterpret_cast<float4*>(dst + (size_t)r0 * 128 + tc8) = f0;
            *reinterpret_cast<float4*>(dst + (size_t)r0 * 128 + tc8 + 4) = f1;
        }
        if (r0 + 1 < N) {
            float4 f0 = make_float4(uhi(acc[0][p]) + bv[0], uhi(acc[1][p]) + bv[1],
                                    uhi(acc[2][p]) + bv[2], uhi(acc[3][p]) + bv[3]);
            float4 f1 = make_float4(uhi(acc[4][p]) + bv[4], uhi(acc[5][p]) + bv[5],
                                    uhi(acc[6][p]) + bv[6], uhi(acc[7][p]) + bv[7]);
            *reinterpret_cast<float4*>(dst + (size_t)(r0 + 1) * 128 + tc8) = f0;
            *reinterpret_cast<float4*>(dst + (size_t)(r0 + 1) * 128 + tc8 + 4) = f1;
        }
    }
}

#define GEMM_PROLOG() \
    int t = threadIdx.x; \
    int tc8 = (t & 15) * 8, tr8 = (t >> 4) * 8; \
    int base = blockIdx.x * BM; \
    ull acc[8][4]; \
    _Pragma("unroll") \
    for (int c = 0; c < 8; c++) { acc[c][0]=0; acc[c][1]=0; acc[c][2]=0; acc[c][3]=0; }

// ---------------- K1: hpre = vf @ w1^T + b1 ----------------
__global__ __launch_bounds__(256, 2) void k_gemm1(const float* __restrict__ vf,
                                                  const float* __restrict__ w1,
                                                  const float* __restrict__ b1, int N) {
    __shared__ __align__(16) float sAT[KC][BM];
    __shared__ __align__(16) float sBT[KC][BM];
    GEMM_PROLOG();
    for (int ck = 0; ck < C3D; ck += KC) {
        load_T(sAT, vf, C3D, base, N, ck, t);
        load_T(sBT, w1, C3D, 0, 1 << 30, ck, t);
        __syncthreads();
        gemm_chunk(sAT, sBT, acc, tr8, tc8);
        __syncthreads();
    }
    store_tile(g_hpre, acc, b1, base, N, tr8, tc8);
}

// ---------------- stats over a [N,128] array ----------------
// src==nullptr => g_hpre (must resolve __device__ symbol in device code;
// host-side symbol becomes ATS-readable host shadow => silent garbage)
__global__ __launch_bounds__(128) void k_stats(const float* src, int off,
                                               int N, int rpb) {
    if (src == nullptr) src = g_hpre;
    __shared__ float ss[128], sq[128];
    int t = threadIdx.x;
    ss[t] = 0.f; sq[t] = 0.f;
    __syncthreads();
    int q4 = (t & 31) * 4, rg = t >> 5;
    long r0 = (long)blockIdx.x * rpb;
    long r1 = r0 + rpb; if (r1 > N) r1 = N;
    float s0=0,s1=0,s2=0,s3=0, p0=0,p1=0,p2=0,p3=0;
    for (long r = r0 + rg; r < r1; r += 4) {
        float4 v = *reinterpret_cast<const float4*>(src + r * 128 + q4);
        s0 += v.x; s1 += v.y; s2 += v.z; s3 += v.w;
        p0 += v.x * v.x; p1 += v.y * v.y; p2 += v.z * v.z; p3 += v.w * v.w;
    }
    atomicAdd(&ss[q4], s0);     atomicAdd(&ss[q4 + 1], s1);
    atomicAdd(&ss[q4 + 2], s2); atomicAdd(&ss[q4 + 3], s3);
    atomicAdd(&sq[q4], p0);     atomicAdd(&sq[q4 + 1], p1);
    atomicAdd(&sq[q4 + 2], p2); atomicAdd(&sq[q4 + 3], p3);
    __syncthreads();
    atomicAdd(&g_stats[off + t], ss[t]);
    atomicAdd(&g_stats[off + 128 + t], sq[t]);
}

// ---------------- finalize bn stats ----------------
__global__ void k_fin(int which, const float* __restrict__ g,
                      const float* __restrict__ b, int N) {
    int j = threadIdx.x;
    int o = which * 256;
    float invN = 1.f / (float)N;
    float m   = g_stats[o + j] * invN;
    float msq = g_stats[o + 128 + j] * invN;
    float var = msq - m * m;
    float s = __ldg(g + j) * rsqrtf(var + 1e-5f);
    g_bnp[o + j] = s;
    g_bnp[o + 128 + j] = __ldg(b + j) - m * s;
}

// ---------------- K3: vfeat = relu(bn(hpre)) @ w2^T + b2 ----------------
__global__ __launch_bounds__(256, 2) void k_gemm2(const float* __restrict__ w2,
                                                  const float* __restrict__ b2, int N) {
    __shared__ __align__(16) float sAT[KC][BM];
    __shared__ __align__(16) float sBT[KC][BM];
    __shared__ float sS[MID], sH[MID];
    GEMM_PROLOG();
    if (t < 128) { sS[t] = g_bnp[t]; sH[t] = g_bnp[128 + t]; }
    __syncthreads();
    for (int ck = 0; ck < MID; ck += KC) {
        #pragma unroll
        for (int i = 0; i < 2; i++) {   // A loader with bn+relu
            int idx = i * 256 + t;
            int r = idx >> 2, k0 = (idx & 3) * 4;
            float4 v = make_float4(0.f, 0.f, 0.f, 0.f);
            if (base + r < N)
                v = *reinterpret_cast<const float4*>(g_hpre + (size_t)(base + r) * MID + ck + k0);
            int gk = ck + k0;
            v.x = fmaxf(fmaf(v.x, sS[gk],     sH[gk]),     0.f);
            v.y = fmaxf(fmaf(v.y, sS[gk + 1], sH[gk + 1]), 0.f);
            v.z = fmaxf(fmaf(v.z, sS[gk + 2], sH[gk + 2]), 0.f);
            v.w = fmaxf(fmaf(v.w, sS[gk + 3], sH[gk + 3]), 0.f);
            sAT[k0][r] = v.x; sAT[k0+1][r] = v.y; sAT[k0+2][r] = v.z; sAT[k0+3][r] = v.w;
        }
        load_T(sBT, w2, MID, 0, 1 << 30, ck, t);
        __syncthreads();
        gemm_chunk(sAT, sBT, acc, tr8, tc8);
        __syncthreads();
    }
    store_tile(g_vfeat, acc, b2, base, N, tr8, tc8);
}

// ---------------- K4: projection + bilinear gather -> ifeat ----------------
__global__ __launch_bounds__(256) void k_sample(const int* __restrict__ coords,
                                                const float* __restrict__ P2, int N) {
    int j  = threadIdx.x & 127;
    int rr = threadIdx.x >> 7;
    int row0 = blockIdx.x * 64;
    for (int r = rr; r < 64; r += 2) {
        int row = row0 + r;
        if (row >= N) break;
        int4 c4 = __ldg(reinterpret_cast<const int4*>(coords + (size_t)row * 4));
        int b = c4.x;
        float p0 = (float)c4.y * 0.05f;
        float p1 = (float)c4.z * 0.05f - 40.f;
        float p2 = (float)c4.w * 0.1f  - 3.f;
        const float* P = P2 + b * 12;
        float cam0 = __ldg(P+0)*p0 + __ldg(P+1)*p1 + __ldg(P+2)*p2  + __ldg(P+3);
        float cam1 = __ldg(P+4)*p0 + __ldg(P+5)*p1 + __ldg(P+6)*p2  + __ldg(P+7);
        float cam2 = __ldg(P+8)*p0 + __ldg(P+9)*p1 + __ldg(P+10)*p2 + __ldg(P+11);
        float d = cam2 + 1e-8f;
        float u = cam0 / d;
        float v = cam1 / d;
        float gx = u / (float)W_ * 2.f - 1.f; gx = fminf(fmaxf(gx, -1.f), 1.f);
        float gy = v / (float)H_ * 2.f - 1.f; gy = fminf(fmaxf(gy, -1.f), 1.f);
        float ix = ((gx + 1.f) * (float)W_ - 1.f) * 0.5f;
        float iy = ((gy + 1.f) * (float)H_ - 1.f) * 0.5f;
        float x0f = floorf(ix), y0f = floorf(iy);
        float wx = ix - x0f, wy = iy - y0f;
        int x0 = (int)x0f, y0 = (int)y0f;
        float acc = 0.f;
        #pragma unroll
        for (int cy = 0; cy < 2; cy++) {
            #pragma unroll
            for (int cx = 0; cx < 2; cx++) {
                int yc = y0 + cy, xc = x0 + cx;
                float wgt = (cx ? wx : 1.f - wx) * (cy ? wy : 1.f - wy);
                if (xc >= 0 && xc < W_ && yc >= 0 && yc < H_) {
                    acc = fmaf(wgt,
                               g_imgT[(((size_t)(b * H_ + yc)) * W_ + xc) * C2D + j],
                               acc);
                }
            }
        }
        g_ifeat[(size_t)row * C2D + j] = acc;
    }
}

// ---------------- K5: attention scalar (GEMM + 128->1 + sigmoid) ----------------
__global__ __launch_bounds__(256, 2) void k_att(const float* __restrict__ aw1,
                                                const float* __restrict__ ab1,
                                                const float* __restrict__ aw2,
                                                const float* __restrict__ ab2, int N) {
    __shared__ __align__(16) float sAT[KC][BM];
    __shared__ __align__(16) float sBT[KC][BM];
    __shared__ float sred[BM][17];
    GEMM_PROLOG();
    for (int ck = 0; ck < 256; ck += KC) {
        const float* src = (ck < 128) ? g_vfeat : g_ifeat;
        int ko = (ck < 128) ? ck : ck - 128;
        load_T(sAT, src, 128, base, N, ko, t);
        load_T(sBT, aw1, 256, 0, 1 << 30, ck, t);
        __syncthreads();
        gemm_chunk(sAT, sBT, acc, tr8, tc8);
        __syncthreads();
    }
    float4 bb0 = *reinterpret_cast<const float4*>(ab1 + tc8);
    float4 bb1 = *reinterpret_cast<const float4*>(ab1 + tc8 + 4);
    float bv[8] = {bb0.x, bb0.y, bb0.z, bb0.w, bb1.x, bb1.y, bb1.z, bb1.w};
    float4 ww0 = *reinterpret_cast<const float4*>(aw2 + tc8);
    float4 ww1 = *reinterpret_cast<const float4*>(aw2 + tc8 + 4);
    float wv[8] = {ww0.x, ww0.y, ww0.z, ww0.w, ww1.x, ww1.y, ww1.z, ww1.w};
    #pragma unroll
    for (int p = 0; p < 4; p++) {
        float slo = 0.f, shi = 0.f;
        #pragma unroll
        for (int c = 0; c < 8; c++) {
            slo += fmaxf(ulo(acc[c][p]) + bv[c], 0.f) * wv[c];
            shi += fmaxf(uhi(acc[c][p]) + bv[c], 0.f) * wv[c];
        }
        sred[tr8 + 2 * p][t & 15]     = slo;
        sred[tr8 + 2 * p + 1][t & 15] = shi;
    }
    __syncthreads();
    if (t < 128 && base + t < N) {
        float s = __ldg(ab2);
        #pragma unroll
        for (int i = 0; i < 16; i++) s += sred[t][i];
        g_att[base + t] = 1.f / (1.f + expf(-s));
    }
}

// ---------------- K6: fused GEMM -> out_pre ----------------
__global__ __launch_bounds__(256, 2) void k_fuse(const float* __restrict__ fw,
                                                 const float* __restrict__ fb,
                                                 float* __restrict__ out, int N) {
    __shared__ __align__(16) float sAT[KC][BM];
    __shared__ __align__(16) float sBT[KC][BM];
    __shared__ float sa[BM];
    GEMM_PROLOG();
    if (t < 128) sa[t] = (base + t < N) ? g_att[base + t] : 0.f;
    __syncthreads();
    for (int ck = 0; ck < 256; ck += KC) {
        bool isv = (ck < 128);
        const float* src = isv ? g_vfeat : g_ifeat;
        int ko = isv ? ck : ck - 128;
        #pragma unroll
        for (int i = 0; i < 2; i++) {   // A loader with attention scaling
            int idx = i * 256 + t;
            int r = idx >> 2, k0 = (idx & 3) * 4;
            float4 v = make_float4(0.f, 0.f, 0.f, 0.f);
            float m = 0.f;
            if (base + r < N) {
                v = *reinterpret_cast<const float4*>(src + (size_t)(base + r) * 128 + ko + k0);
                m = isv ? sa[r] : 1.f - sa[r];
            }
            sAT[k0][r] = v.x * m; sAT[k0+1][r] = v.y * m;
            sAT[k0+2][r] = v.z * m; sAT[k0+3][r] = v.w * m;
        }
        load_T(sBT, fw, 256, 0, 1 << 30, ck, t);
        __syncthreads();
        gemm_chunk(sAT, sBT, acc, tr8, tc8);
        __syncthreads();
    }
    store_tile(out, acc, fb, base, N, tr8, tc8);
}

// ---------------- K8: in-place final bn + relu ----------------
__global__ void k_bnrelu(float* __restrict__ out, long total4) {
    long i = (long)blockIdx.x * blockDim.x + threadIdx.x;
    if (i < total4) {
        int cb = (int)((i & 31) * 4);
        float4 v = reinterpret_cast<float4*>(out)[i];
        v.x = fmaxf(fmaf(v.x, g_bnp[256 + cb],     g_bnp[384 + cb]),     0.f);
        v.y = fmaxf(fmaf(v.y, g_bnp[256 + cb + 1], g_bnp[384 + cb + 1]), 0.f);
        v.z = fmaxf(fmaf(v.z, g_bnp[256 + cb + 2], g_bnp[384 + cb + 2]), 0.f);
        v.w = fmaxf(fmaf(v.w, g_bnp[256 + cb + 3], g_bnp[384 + cb + 3]), 0.f);
        reinterpret_cast<float4*>(out)[i] = v;
    }
}

// ---------------- launch ----------------
extern "C" void kernel_launch(void* const* d_in, const int* in_sizes, int n_in,
                              void* d_out, int out_size) {
    const float* vf     = (const float*)d_in[0];
    const int*   coords = (const int*)  d_in[1];
    const float* img    = (const float*)d_in[2];
    const float* P2     = (const float*)d_in[3];
    const float* vt_w1  = (const float*)d_in[4];
    const float* vt_b1  = (const float*)d_in[5];
    const float* bn1_g  = (const float*)d_in[6];
    const float* bn1_b  = (const float*)d_in[7];
    const float* vt_w2  = (const float*)d_in[8];
    const float* vt_b2  = (const float*)d_in[9];
    const float* att_w1 = (const float*)d_in[10];
    const float* att_b1 = (const float*)d_in[11];
    const float* att_w2 = (const float*)d_in[12];
    const float* att_b2 = (const float*)d_in[13];
    const float* fus_w  = (const float*)d_in[14];
    const float* fus_b  = (const float*)d_in[15];
    const float* bnf_g  = (const float*)d_in[16];
    const float* bnf_b  = (const float*)d_in[17];

    int N = in_sizes[1] / 4;
    float* out = (float*)d_out;
    int nblk = (N + BM - 1) / BM;
    int sblk = 512, rpb = (N + sblk - 1) / sblk;

    k_transpose<<<dim3((W_ + 31) / 32, C2D / 32, B_ * H_), dim3(32, 8)>>>(img);
    k_zero<<<1, 512>>>();
    k_gemm1<<<nblk, 256>>>(vf, vt_w1, vt_b1, N);
    k_stats<<<sblk, 128>>>(nullptr, 0, N, rpb);   // nullptr => g_hpre
    k_fin<<<1, 128>>>(0, bn1_g, bn1_b, N);
    k_gemm2<<<nblk, 256>>>(vt_w2, vt_b2, N);
    k_sample<<<(N + 63) / 64, 256>>>(coords, P2, N);
    k_att<<<nblk, 256>>>(att_w1, att_b1, att_w2, att_b2, N);
    k_fuse<<<nblk, 256>>>(fus_w, fus_b, out, N);
    k_stats<<<sblk, 128>>>(out, 256, N, rpb);
    k_fin<<<1, 128>>>(1, bnf_g, bnf_b, N);
    long total4 = (long)N * 32;
    k_bnrelu<<<(unsigned)((total4 + 255) / 256), 256>>>(out, total4);
}

// round 11
// speedup vs baseline: 6.8058x; 1.0428x over previous
#include <cuda_runtime.h>
#include <math.h>
#include <stdint.h>

// ---------------- problem constants ----------------
#define NMAX 200000
#define B_   4
#define C2D  128
#define H_   96
#define W_   312
#define MID  128
#define C3D  64
#define BM   128
#define KC   16

typedef unsigned long long ull;

__device__ __forceinline__ void fma2(ull& d, ull a, ull b) {
    asm("fma.rn.f32x2 %0, %1, %2, %0;" : "+l"(d) : "l"(a), "l"(b));
}
__device__ __forceinline__ ull dup2(float b) {
    ull r; asm("mov.b64 %0, {%1, %1};" : "=l"(r) : "f"(b)); return r;
}
__device__ __forceinline__ float ulo(ull a) { return __uint_as_float((unsigned)a); }
__device__ __forceinline__ float uhi(ull a) { return __uint_as_float((unsigned)(a >> 32)); }

// ---------------- scratch ----------------
__device__ __align__(16) float g_imgT[(size_t)B_ * H_ * W_ * C2D];
__device__ __align__(16) float g_hpre[(size_t)NMAX * MID];
__device__ __align__(16) float g_vfeat[(size_t)NMAX * MID];
__device__ __align__(16) float g_ifeat[(size_t)NMAX * C2D];
__device__ float g_att[NMAX];
__device__ float g_stats[512];
__device__ float g_bnp[512];

__global__ void k_zero() {
    if (threadIdx.x < 512) g_stats[threadIdx.x] = 0.f;
}

// ---------------- K0: image transpose [B,C,H,W] -> [B,H,W,C] ----------------
__global__ void k_transpose(const float* __restrict__ img) {
    __shared__ float tile[32][33];
    int bh = blockIdx.z;
    int b  = bh / H_;
    int hh = bh % H_;
    int w0 = blockIdx.x * 32;
    int c0 = blockIdx.y * 32;
    int tx = threadIdx.x, ty = threadIdx.y;
    #pragma unroll
    for (int i = 0; i < 32; i += 8) {
        int c = c0 + ty + i;
        int w = w0 + tx;
        float v = 0.f;
        if (w < W_) v = img[((size_t)(b * C2D + c) * H_ + hh) * W_ + w];
        tile[ty + i][tx] = v;
    }
    __syncthreads();
    #pragma unroll
    for (int i = 0; i < 32; i += 8) {
        int w = w0 + ty + i;
        int c = c0 + tx;
        if (w < W_)
            g_imgT[((size_t)bh * W_ + w) * C2D + c] = tile[tx][ty + i];
    }
}

// ---------------- shared GEMM pieces ----------------
// per-thread fragment of one 128xKC chunk: 2 float4
__device__ __forceinline__ void ldg_frag(float4 f[2], const float* __restrict__ src,
                                         int ld, int base, int N, int kofs, int t) {
    #pragma unroll
    for (int i = 0; i < 2; i++) {
        int idx = i * 256 + t;
        int r = idx >> 2, k0 = (idx & 3) * 4;
        f[i] = make_float4(0.f, 0.f, 0.f, 0.f);
        if (base + r < N)
            f[i] = *reinterpret_cast<const float4*>(src + (size_t)(base + r) * ld + kofs + k0);
    }
}
__device__ __forceinline__ void sts_frag(float (*sT)[BM], const float4 f[2], int t) {
    #pragma unroll
    for (int i = 0; i < 2; i++) {
        int idx = i * 256 + t;
        int r = idx >> 2, k0 = (idx & 3) * 4;
        sT[k0][r] = f[i].x; sT[k0+1][r] = f[i].y; sT[k0+2][r] = f[i].z; sT[k0+3][r] = f[i].w;
    }
}

// f32x2 core: acc[c][p] holds rows (tr8+2p, tr8+2p+1) for column tc8+c.
__device__ __forceinline__ void gemm_chunk(const float (*sAT)[BM], const float (*sBT)[BM],
                                           ull acc[8][4], int tr8, int tc8) {
    #pragma unroll
    for (int k = 0; k < KC; k++) {
        ulonglong2 aA = *reinterpret_cast<const ulonglong2*>(&sAT[k][tr8]);
        ulonglong2 aB = *reinterpret_cast<const ulonglong2*>(&sAT[k][tr8 + 4]);
        float4 b0 = *reinterpret_cast<const float4*>(&sBT[k][tc8]);
        float4 b1 = *reinterpret_cast<const float4*>(&sBT[k][tc8 + 4]);
        float bs[8] = {b0.x, b0.y, b0.z, b0.w, b1.x, b1.y, b1.z, b1.w};
        #pragma unroll
        for (int c = 0; c < 8; c++) {
            ull bd = dup2(bs[c]);
            fma2(acc[c][0], aA.x, bd);
            fma2(acc[c][1], aA.y, bd);
            fma2(acc[c][2], aB.x, bd);
            fma2(acc[c][3], aB.y, bd);
        }
    }
}

// store 8x8 tile (+bias); lo lane = even row of pair
__device__ __forceinline__ void store_tile(float* __restrict__ dst, const ull acc[8][4],
                                           const float* __restrict__ bias,
                                           int base, int N, int tr8, int tc8) {
    float4 bb0 = *reinterpret_cast<const float4*>(bias + tc8);
    float4 bb1 = *reinterpret_cast<const float4*>(bias + tc8 + 4);
    float bv[8] = {bb0.x, bb0.y, bb0.z, bb0.w, bb1.x, bb1.y, bb1.z, bb1.w};
    #pragma unroll
    for (int p = 0; p < 4; p++) {
        int r0 = base + tr8 + 2 * p;
        if (r0 < N) {
            float4 f0 = make_float4(ulo(acc[0][p]) + bv[0], ulo(acc[1][p]) + bv[1],
                                    ulo(acc[2][p]) + bv[2], ulo(acc[3][p]) + bv[3]);
            float4 f1 = make_float4(ulo(acc[4][p]) + bv[4], ulo(acc[5][p]) + bv[5],
                                    ulo(acc[6][p]) + bv[6], ulo(acc[7][p]) + bv[7]);
            *reinterpret_cast<float4*>(dst + (size_t)r0 * 128 + tc8) = f0;
            *reinterpret_cast<float4*>(dst + (size_t)r0 * 128 + tc8 + 4) = f1;
        }
        if (r0 + 1 < N) {
            float4 f0 = make_float4(uhi(acc[0][p]) + bv[0], uhi(acc[1][p]) + bv[1],
                                    uhi(acc[2][p]) + bv[2], uhi(acc[3][p]) + bv[3]);
            float4 f1 = make_float4(uhi(acc[4][p]) + bv[4], uhi(acc[5][p]) + bv[5],
                                    uhi(acc[6][p]) + bv[6], uhi(acc[7][p]) + bv[7]);
            *reinterpret_cast<float4*>(dst + (size_t)(r0 + 1) * 128 + tc8) = f0;
            *reinterpret_cast<float4*>(dst + (size_t)(r0 + 1) * 128 + tc8 + 4) = f1;
        }
    }
}

#define GEMM_PROLOG() \
    int t = threadIdx.x; \
    int tc8 = (t & 15) * 8, tr8 = (t >> 4) * 8; \
    int base = blockIdx.x * BM; \
    ull acc[8][4]; \
    _Pragma("unroll") \
    for (int c = 0; c < 8; c++) { acc[c][0]=0; acc[c][1]=0; acc[c][2]=0; acc[c][3]=0; }

// ---------------- K1: hpre = vf @ w1^T + b1 (double-buffered) ----------------
__global__ __launch_bounds__(256, 2) void k_gemm1(const float* __restrict__ vf,
                                                  const float* __restrict__ w1,
                                                  const float* __restrict__ b1, int N) {
    __shared__ __align__(16) float sAT[2][KC][BM];
    __shared__ __align__(16) float sBT[2][KC][BM];
    GEMM_PROLOG();
    const int nc = C3D / KC;   // 4
    float4 fa[2], fb[2];
    ldg_frag(fa, vf, C3D, base, N, 0, t);
    ldg_frag(fb, w1, C3D, 0, 1 << 30, 0, t);
    sts_frag(sAT[0], fa, t); sts_frag(sBT[0], fb, t);
    ldg_frag(fa, vf, C3D, base, N, KC, t);
    ldg_frag(fb, w1, C3D, 0, 1 << 30, KC, t);
    __syncthreads();
    for (int c = 0; c < nc; c++) {
        gemm_chunk(sAT[c & 1], sBT[c & 1], acc, tr8, tc8);
        if (c + 1 < nc) {
            sts_frag(sAT[(c + 1) & 1], fa, t); sts_frag(sBT[(c + 1) & 1], fb, t);
            if (c + 2 < nc) {
                ldg_frag(fa, vf, C3D, base, N, (c + 2) * KC, t);
                ldg_frag(fb, w1, C3D, 0, 1 << 30, (c + 2) * KC, t);
            }
            __syncthreads();
        }
    }
    store_tile(g_hpre, acc, b1, base, N, tr8, tc8);
}

// ---------------- stats over a [N,128] array ----------------
// src==nullptr => g_hpre (device-side symbol resolve; host-side symbol is
// an ATS-readable host shadow on GB300 => silent garbage)
__global__ __launch_bounds__(128) void k_stats(const float* src, int off,
                                               int N, int rpb) {
    if (src == nullptr) src = g_hpre;
    __shared__ float ss[128], sq[128];
    int t = threadIdx.x;
    ss[t] = 0.f; sq[t] = 0.f;
    __syncthreads();
    int q4 = (t & 31) * 4, rg = t >> 5;
    long r0 = (long)blockIdx.x * rpb;
    long r1 = r0 + rpb; if (r1 > N) r1 = N;
    float s0=0,s1=0,s2=0,s3=0, p0=0,p1=0,p2=0,p3=0;
    for (long r = r0 + rg; r < r1; r += 4) {
        float4 v = *reinterpret_cast<const float4*>(src + r * 128 + q4);
        s0 += v.x; s1 += v.y; s2 += v.z; s3 += v.w;
        p0 += v.x * v.x; p1 += v.y * v.y; p2 += v.z * v.z; p3 += v.w * v.w;
    }
    atomicAdd(&ss[q4], s0);     atomicAdd(&ss[q4 + 1], s1);
    atomicAdd(&ss[q4 + 2], s2); atomicAdd(&ss[q4 + 3], s3);
    atomicAdd(&sq[q4], p0);     atomicAdd(&sq[q4 + 1], p1);
    atomicAdd(&sq[q4 + 2], p2); atomicAdd(&sq[q4 + 3], p3);
    __syncthreads();
    atomicAdd(&g_stats[off + t], ss[t]);
    atomicAdd(&g_stats[off + 128 + t], sq[t]);
}

// ---------------- finalize bn stats ----------------
__global__ void k_fin(int which, const float* __restrict__ g,
                      const float* __restrict__ b, int N) {
    int j = threadIdx.x;
    int o = which * 256;
    float invN = 1.f / (float)N;
    float m   = g_stats[o + j] * invN;
    float msq = g_stats[o + 128 + j] * invN;
    float var = msq - m * m;
    float s = __ldg(g + j) * rsqrtf(var + 1e-5f);
    g_bnp[o + j] = s;
    g_bnp[o + 128 + j] = __ldg(b + j) - m * s;
}

// ---------------- K3: vfeat = relu(bn(hpre)) @ w2^T + b2 (double-buffered) ----------------
__global__ __launch_bounds__(256, 2) void k_gemm2(const float* __restrict__ w2,
                                                  const float* __restrict__ b2, int N) {
    __shared__ __align__(16) float sAT[2][KC][BM];
    __shared__ __align__(16) float sBT[2][KC][BM];
    __shared__ float sS[MID], sH[MID];
    GEMM_PROLOG();
    if (t < 128) { sS[t] = g_bnp[t]; sH[t] = g_bnp[128 + t]; }
    __syncthreads();
    const int nc = MID / KC;   // 8
    // A loader with bn+relu applied on registers at LDG time
    auto ldgA = [&](float4 f[2], int kofs) {
        ldg_frag(f, g_hpre, MID, base, N, kofs, t);
        #pragma unroll
        for (int i = 0; i < 2; i++) {
            int idx = i * 256 + t;
            int gk = kofs + (idx & 3) * 4;
            f[i].x = fmaxf(fmaf(f[i].x, sS[gk],     sH[gk]),     0.f);
            f[i].y = fmaxf(fmaf(f[i].y, sS[gk + 1], sH[gk + 1]), 0.f);
            f[i].z = fmaxf(fmaf(f[i].z, sS[gk + 2], sH[gk + 2]), 0.f);
            f[i].w = fmaxf(fmaf(f[i].w, sS[gk + 3], sH[gk + 3]), 0.f);
        }
    };
    float4 fa[2], fb[2];
    ldgA(fa, 0);
    ldg_frag(fb, w2, MID, 0, 1 << 30, 0, t);
    sts_frag(sAT[0], fa, t); sts_frag(sBT[0], fb, t);
    ldgA(fa, KC);
    ldg_frag(fb, w2, MID, 0, 1 << 30, KC, t);
    __syncthreads();
    for (int c = 0; c < nc; c++) {
        gemm_chunk(sAT[c & 1], sBT[c & 1], acc, tr8, tc8);
        if (c + 1 < nc) {
            sts_frag(sAT[(c + 1) & 1], fa, t); sts_frag(sBT[(c + 1) & 1], fb, t);
            if (c + 2 < nc) {
                ldgA(fa, (c + 2) * KC);
                ldg_frag(fb, w2, MID, 0, 1 << 30, (c + 2) * KC, t);
            }
            __syncthreads();
        }
    }
    store_tile(g_vfeat, acc, b2, base, N, tr8, tc8);
}

// ---------------- K4: projection + bilinear gather -> ifeat ----------------
__global__ __launch_bounds__(256) void k_sample(const int* __restrict__ coords,
                                                const float* __restrict__ P2, int N) {
    int j  = threadIdx.x & 127;
    int rr = threadIdx.x >> 7;
    int row0 = blockIdx.x * 64;
    for (int r = rr; r < 64; r += 2) {
        int row = row0 + r;
        if (row >= N) break;
        int4 c4 = __ldg(reinterpret_cast<const int4*>(coords + (size_t)row * 4));
        int b = c4.x;
        float p0 = (float)c4.y * 0.05f;
        float p1 = (float)c4.z * 0.05f - 40.f;
        float p2 = (float)c4.w * 0.1f  - 3.f;
        const float* P = P2 + b * 12;
        float cam0 = __ldg(P+0)*p0 + __ldg(P+1)*p1 + __ldg(P+2)*p2  + __ldg(P+3);
        float cam1 = __ldg(P+4)*p0 + __ldg(P+5)*p1 + __ldg(P+6)*p2  + __ldg(P+7);
        float cam2 = __ldg(P+8)*p0 + __ldg(P+9)*p1 + __ldg(P+10)*p2 + __ldg(P+11);
        float d = cam2 + 1e-8f;
        float u = cam0 / d;
        float v = cam1 / d;
        float gx = u / (float)W_ * 2.f - 1.f; gx = fminf(fmaxf(gx, -1.f), 1.f);
        float gy = v / (float)H_ * 2.f - 1.f; gy = fminf(fmaxf(gy, -1.f), 1.f);
        float ix = ((gx + 1.f) * (float)W_ - 1.f) * 0.5f;
        float iy = ((gy + 1.f) * (float)H_ - 1.f) * 0.5f;
        float x0f = floorf(ix), y0f = floorf(iy);
        float wx = ix - x0f, wy = iy - y0f;
        int x0 = (int)x0f, y0 = (int)y0f;
        float acc = 0.f;
        #pragma unroll
        for (int cy = 0; cy < 2; cy++) {
            #pragma unroll
            for (int cx = 0; cx < 2; cx++) {
                int yc = y0 + cy, xc = x0 + cx;
                float wgt = (cx ? wx : 1.f - wx) * (cy ? wy : 1.f - wy);
                if (xc >= 0 && xc < W_ && yc >= 0 && yc < H_) {
                    acc = fmaf(wgt,
                               g_imgT[(((size_t)(b * H_ + yc)) * W_ + xc) * C2D + j],
                               acc);
                }
            }
        }
        g_ifeat[(size_t)row * C2D + j] = acc;
    }
}

// shared A loader for the concat [vfeat | ifeat] inputs (att / fuse)
__device__ __forceinline__ void ldg_cat(float4 f[2], int base, int N, int ck, int t) {
    const float* src = (ck < 128) ? g_vfeat : g_ifeat;
    int ko = (ck < 128) ? ck : ck - 128;
    ldg_frag(f, src, 128, base, N, ko, t);
}

// ---------------- K5: attention scalar (double-buffered) ----------------
__global__ __launch_bounds__(256, 2) void k_att(const float* __restrict__ aw1,
                                                const float* __restrict__ ab1,
                                                const float* __restrict__ aw2,
                                                const float* __restrict__ ab2, int N) {
    __shared__ __align__(16) float sAT[2][KC][BM];
    __shared__ __align__(16) float sBT[2][KC][BM];
    __shared__ float sred[BM][17];
    GEMM_PROLOG();
    const int nc = 256 / KC;   // 16
    float4 fa[2], fb[2];
    ldg_cat(fa, base, N, 0, t);
    ldg_frag(fb, aw1, 256, 0, 1 << 30, 0, t);
    sts_frag(sAT[0], fa, t); sts_frag(sBT[0], fb, t);
    ldg_cat(fa, base, N, KC, t);
    ldg_frag(fb, aw1, 256, 0, 1 << 30, KC, t);
    __syncthreads();
    for (int c = 0; c < nc; c++) {
        gemm_chunk(sAT[c & 1], sBT[c & 1], acc, tr8, tc8);
        if (c + 1 < nc) {
            sts_frag(sAT[(c + 1) & 1], fa, t); sts_frag(sBT[(c + 1) & 1], fb, t);
            if (c + 2 < nc) {
                ldg_cat(fa, base, N, (c + 2) * KC, t);
                ldg_frag(fb, aw1, 256, 0, 1 << 30, (c + 2) * KC, t);
            }
            __syncthreads();
        }
    }
    float4 bb0 = *reinterpret_cast<const float4*>(ab1 + tc8);
    float4 bb1 = *reinterpret_cast<const float4*>(ab1 + tc8 + 4);
    float bv[8] = {bb0.x, bb0.y, bb0.z, bb0.w, bb1.x, bb1.y, bb1.z, bb1.w};
    float4 ww0 = *reinterpret_cast<const float4*>(aw2 + tc8);
    float4 ww1 = *reinterpret_cast<const float4*>(aw2 + tc8 + 4);
    float wv[8] = {ww0.x, ww0.y, ww0.z, ww0.w, ww1.x, ww1.y, ww1.z, ww1.w};
    #pragma unroll
    for (int p = 0; p < 4; p++) {
        float slo = 0.f, shi = 0.f;
        #pragma unroll
        for (int c = 0; c < 8; c++) {
            slo += fmaxf(ulo(acc[c][p]) + bv[c], 0.f) * wv[c];
            shi += fmaxf(uhi(acc[c][p]) + bv[c], 0.f) * wv[c];
        }
        sred[tr8 + 2 * p][t & 15]     = slo;
        sred[tr8 + 2 * p + 1][t & 15] = shi;
    }
    __syncthreads();
    if (t < 128 && base + t < N) {
        float s = __ldg(ab2);
        #pragma unroll
        for (int i = 0; i < 16; i++) s += sred[t][i];
        g_att[base + t] = 1.f / (1.f + expf(-s));
    }
}

// ---------------- K6: fused GEMM -> out_pre (double-buffered) ----------------
__global__ __launch_bounds__(256, 2) void k_fuse(const float* __restrict__ fw,
                                                 const float* __restrict__ fb,
                                                 float* __restrict__ out, int N) {
    __shared__ __align__(16) float sAT[2][KC][BM];
    __shared__ __align__(16) float sBT[2][KC][BM];
    __shared__ float sa[BM];
    GEMM_PROLOG();
    if (t < 128) sa[t] = (base + t < N) ? g_att[base + t] : 0.f;
    __syncthreads();
    const int nc = 256 / KC;   // 16
    // A loader with attention scaling applied on registers at LDG time
    auto ldgA = [&](float4 f[2], int ck) {
        ldg_cat(f, base, N, ck, t);
        bool isv = (ck < 128);
        #pragma unroll
        for (int i = 0; i < 2; i++) {
            int idx = i * 256 + t;
            int r = idx >> 2;
            float a = sa[r];
            float m = isv ? a : 1.f - a;
            f[i].x *= m; f[i].y *= m; f[i].z *= m; f[i].w *= m;
        }
    };
    float4 fa[2], fb2[2];
    ldgA(fa, 0);
    ldg_frag(fb2, fw, 256, 0, 1 << 30, 0, t);
    sts_frag(sAT[0], fa, t); sts_frag(sBT[0], fb2, t);
    ldgA(fa, KC);
    ldg_frag(fb2, fw, 256, 0, 1 << 30, KC, t);
    __syncthreads();
    for (int c = 0; c < nc; c++) {
        gemm_chunk(sAT[c & 1], sBT[c & 1], acc, tr8, tc8);
        if (c + 1 < nc) {
            sts_frag(sAT[(c + 1) & 1], fa, t); sts_frag(sBT[(c + 1) & 1], fb2, t);
            if (c + 2 < nc) {
                ldgA(fa, (c + 2) * KC);
                ldg_frag(fb2, fw, 256, 0, 1 << 30, (c + 2) * KC, t);
            }
            __syncthreads();
        }
    }
    store_tile(out, acc, fb, base, N, tr8, tc8);
}

// ---------------- K8: in-place final bn + relu ----------------
__global__ void k_bnrelu(float* __restrict__ out, long total4) {
    long i = (long)blockIdx.x * blockDim.x + threadIdx.x;
    if (i < total4) {
        int cb = (int)((i & 31) * 4);
        float4 v = reinterpret_cast<float4*>(out)[i];
        v.x = fmaxf(fmaf(v.x, g_bnp[256 + cb],     g_bnp[384 + cb]),     0.f);
        v.y = fmaxf(fmaf(v.y, g_bnp[256 + cb + 1], g_bnp[384 + cb + 1]), 0.f);
        v.z = fmaxf(fmaf(v.z, g_bnp[256 + cb + 2], g_bnp[384 + cb + 2]), 0.f);
        v.w = fmaxf(fmaf(v.w, g_bnp[256 + cb + 3], g_bnp[384 + cb + 3]), 0.f);
        reinterpret_cast<float4*>(out)[i] = v;
    }
}

// ---------------- launch ----------------
extern "C" void kernel_launch(void* const* d_in, const int* in_sizes, int n_in,
                              void* d_out, int out_size) {
    const float* vf     = (const float*)d_in[0];
    const int*   coords = (const int*)  d_in[1];
    const float* img    = (const float*)d_in[2];
    const float* P2     = (const float*)d_in[3];
    const float* vt_w1  = (const float*)d_in[4];
    const float* vt_b1  = (const float*)d_in[5];
    const float* bn1_g  = (const float*)d_in[6];
    const float* bn1_b  = (const float*)d_in[7];
    const float* vt_w2  = (const float*)d_in[8];
    const float* vt_b2  = (const float*)d_in[9];
    const float* att_w1 = (const float*)d_in[10];
    const float* att_b1 = (const float*)d_in[11];
    const float* att_w2 = (const float*)d_in[12];
    const float* att_b2 = (const float*)d_in[13];
    const float* fus_w  = (const float*)d_in[14];
    const float* fus_b  = (const float*)d_in[15];
    const float* bnf_g  = (const float*)d_in[16];
    const float* bnf_b  = (const float*)d_in[17];

    int N = in_sizes[1] / 4;
    float* out = (float*)d_out;
    int nblk = (N + BM - 1) / BM;
    int sblk = 512, rpb = (N + sblk - 1) / sblk;

    k_transpose<<<dim3((W_ + 31) / 32, C2D / 32, B_ * H_), dim3(32, 8)>>>(img);
    k_zero<<<1, 512>>>();
    k_gemm1<<<nblk, 256>>>(vf, vt_w1, vt_b1, N);
    k_stats<<<sblk, 128>>>(nullptr, 0, N, rpb);   // nullptr => g_hpre
    k_fin<<<1, 128>>>(0, bn1_g, bn1_b, N);
    k_gemm2<<<nblk, 256>>>(vt_w2, vt_b2, N);
    k_sample<<<(N + 63) / 64, 256>>>(coords, P2, N);
    k_att<<<nblk, 256>>>(att_w1, att_b1, att_w2, att_b2, N);
    k_fuse<<<nblk, 256>>>(fus_w, fus_b, out, N);
    k_stats<<<sblk, 128>>>(out, 256, N, rpb);
    k_fin<<<1, 128>>>(1, bnf_g, bnf_b, N);
    long total4 = (long)N * 32;
    k_bnrelu<<<(unsigned)((total4 + 255) / 256), 256>>>(out, total4);
}

// round 12
// speedup vs baseline: 7.6057x; 1.1175x over previous
#include <cuda_runtime.h>
#include <math.h>
#include <stdint.h>

// ---------------- problem constants ----------------
#define NMAX 200000
#define B_   4
#define C2D  128
#define H_   96
#define W_   312
#define MID  128
#define C3D  64
#define BM   128
#define KC   16

typedef unsigned long long ull;

__device__ __forceinline__ void fma2(ull& d, ull a, ull b) {
    asm("fma.rn.f32x2 %0, %1, %2, %0;" : "+l"(d) : "l"(a), "l"(b));
}
__device__ __forceinline__ ull dup2(float b) {
    ull r; asm("mov.b64 %0, {%1, %1};" : "=l"(r) : "f"(b)); return r;
}
__device__ __forceinline__ float ulo(ull a) { return __uint_as_float((unsigned)a); }
__device__ __forceinline__ float uhi(ull a) { return __uint_as_float((unsigned)(a >> 32)); }

// ---------------- scratch ----------------
__device__ __align__(16) float g_imgT[(size_t)B_ * H_ * W_ * C2D];
__device__ __align__(16) float g_hpre[(size_t)NMAX * MID];
__device__ __align__(16) float g_vfeat[(size_t)NMAX * MID];
__device__ __align__(16) float g_ifeat[(size_t)NMAX * C2D];
__device__ float g_att[NMAX];
__device__ float g_stats[512];
__device__ float g_bnp[512];

__global__ void k_zero() {
    if (threadIdx.x < 512) g_stats[threadIdx.x] = 0.f;
}

// ---------------- K0: image transpose [B,C,H,W] -> [B,H,W,C] ----------------
__global__ void k_transpose(const float* __restrict__ img) {
    __shared__ float tile[32][33];
    int bh = blockIdx.z;
    int b  = bh / H_;
    int hh = bh % H_;
    int w0 = blockIdx.x * 32;
    int c0 = blockIdx.y * 32;
    int tx = threadIdx.x, ty = threadIdx.y;
    #pragma unroll
    for (int i = 0; i < 32; i += 8) {
        int c = c0 + ty + i;
        int w = w0 + tx;
        float v = 0.f;
        if (w < W_) v = img[((size_t)(b * C2D + c) * H_ + hh) * W_ + w];
        tile[ty + i][tx] = v;
    }
    __syncthreads();
    #pragma unroll
    for (int i = 0; i < 32; i += 8) {
        int w = w0 + ty + i;
        int c = c0 + tx;
        if (w < W_)
            g_imgT[((size_t)bh * W_ + w) * C2D + c] = tile[tx][ty + i];
    }
}

// ---------------- shared GEMM pieces ----------------
// per-thread fragment of one 128xKC chunk: 2 float4
__device__ __forceinline__ void ldg_frag(float4 f[2], const float* __restrict__ src,
                                         int ld, int base, int N, int kofs, int t) {
    #pragma unroll
    for (int i = 0; i < 2; i++) {
        int idx = i * 256 + t;
        int r = idx >> 2, k0 = (idx & 3) * 4;
        f[i] = make_float4(0.f, 0.f, 0.f, 0.f);
        if (base + r < N)
            f[i] = *reinterpret_cast<const float4*>(src + (size_t)(base + r) * ld + kofs + k0);
    }
}
__device__ __forceinline__ void sts_frag(float (*sT)[BM], const float4 f[2], int t) {
    #pragma unroll
    for (int i = 0; i < 2; i++) {
        int idx = i * 256 + t;
        int r = idx >> 2, k0 = (idx & 3) * 4;
        sT[k0][r] = f[i].x; sT[k0+1][r] = f[i].y; sT[k0+2][r] = f[i].z; sT[k0+3][r] = f[i].w;
    }
}

// f32x2 core, split tile: rows {tr4..+3, tr4+64..+67}, cols {tc4..+3, tc4+64..+67}.
// acc[c][p]: p=0,1 -> row pairs in low group; p=2,3 -> high group.
// B loads now 16B lane stride => conflict-free LDS phases.
__device__ __forceinline__ void gemm_chunk(const float (*sAT)[BM], const float (*sBT)[BM],
                                           ull acc[8][4], int tr4, int tc4) {
    #pragma unroll
    for (int k = 0; k < KC; k++) {
        ulonglong2 aA = *reinterpret_cast<const ulonglong2*>(&sAT[k][tr4]);
        ulonglong2 aB = *reinterpret_cast<const ulonglong2*>(&sAT[k][tr4 + 64]);
        float4 b0 = *reinterpret_cast<const float4*>(&sBT[k][tc4]);
        float4 b1 = *reinterpret_cast<const float4*>(&sBT[k][tc4 + 64]);
        float bs[8] = {b0.x, b0.y, b0.z, b0.w, b1.x, b1.y, b1.z, b1.w};
        #pragma unroll
        for (int c = 0; c < 8; c++) {
            ull bd = dup2(bs[c]);
            fma2(acc[c][0], aA.x, bd);
            fma2(acc[c][1], aA.y, bd);
            fma2(acc[c][2], aB.x, bd);
            fma2(acc[c][3], aB.y, bd);
        }
    }
}

// store split 8x8 tile (+bias); lo lane = even row of pair
__device__ __forceinline__ void store_tile(float* __restrict__ dst, const ull acc[8][4],
                                           const float* __restrict__ bias,
                                           int base, int N, int tr4, int tc4) {
    float4 bb0 = *reinterpret_cast<const float4*>(bias + tc4);
    float4 bb1 = *reinterpret_cast<const float4*>(bias + tc4 + 64);
    float bv[8] = {bb0.x, bb0.y, bb0.z, bb0.w, bb1.x, bb1.y, bb1.z, bb1.w};
    #pragma unroll
    for (int p = 0; p < 4; p++) {
        int rl = (p < 2) ? tr4 + 2 * p : tr4 + 64 + 2 * (p - 2);
        int r0 = base + rl;
        if (r0 < N) {
            float4 f0 = make_float4(ulo(acc[0][p]) + bv[0], ulo(acc[1][p]) + bv[1],
                                    ulo(acc[2][p]) + bv[2], ulo(acc[3][p]) + bv[3]);
            float4 f1 = make_float4(ulo(acc[4][p]) + bv[4], ulo(acc[5][p]) + bv[5],
                                    ulo(acc[6][p]) + bv[6], ulo(acc[7][p]) + bv[7]);
            *reinterpret_cast<float4*>(dst + (size_t)r0 * 128 + tc4) = f0;
            *reinterpret_cast<float4*>(dst + (size_t)r0 * 128 + tc4 + 64) = f1;
        }
        if (r0 + 1 < N) {
            float4 f0 = make_float4(uhi(acc[0][p]) + bv[0], uhi(acc[1][p]) + bv[1],
                                    uhi(acc[2][p]) + bv[2], uhi(acc[3][p]) + bv[3]);
            float4 f1 = make_float4(uhi(acc[4][p]) + bv[4], uhi(acc[5][p]) + bv[5],
                                    uhi(acc[6][p]) + bv[6], uhi(acc[7][p]) + bv[7]);
            *reinterpret_cast<float4*>(dst + (size_t)(r0 + 1) * 128 + tc4) = f0;
            *reinterpret_cast<float4*>(dst + (size_t)(r0 + 1) * 128 + tc4 + 64) = f1;
        }
    }
}

#define GEMM_PROLOG() \
    int t = threadIdx.x; \
    int tc4 = (t & 15) * 4, tr4 = (t >> 4) * 4; \
    int base = blockIdx.x * BM; \
    ull acc[8][4]; \
    _Pragma("unroll") \
    for (int c = 0; c < 8; c++) { acc[c][0]=0; acc[c][1]=0; acc[c][2]=0; acc[c][3]=0; }

// ---------------- K1: hpre = vf @ w1^T + b1 (double-buffered) ----------------
__global__ __launch_bounds__(256, 2) void k_gemm1(const float* __restrict__ vf,
                                                  const float* __restrict__ w1,
                                                  const float* __restrict__ b1, int N) {
    __shared__ __align__(16) float sAT[2][KC][BM];
    __shared__ __align__(16) float sBT[2][KC][BM];
    GEMM_PROLOG();
    const int nc = C3D / KC;   // 4
    float4 fa[2], fb[2];
    ldg_frag(fa, vf, C3D, base, N, 0, t);
    ldg_frag(fb, w1, C3D, 0, 1 << 30, 0, t);
    sts_frag(sAT[0], fa, t); sts_frag(sBT[0], fb, t);
    ldg_frag(fa, vf, C3D, base, N, KC, t);
    ldg_frag(fb, w1, C3D, 0, 1 << 30, KC, t);
    __syncthreads();
    for (int c = 0; c < nc; c++) {
        gemm_chunk(sAT[c & 1], sBT[c & 1], acc, tr4, tc4);
        if (c + 1 < nc) {
            sts_frag(sAT[(c + 1) & 1], fa, t); sts_frag(sBT[(c + 1) & 1], fb, t);
            if (c + 2 < nc) {
                ldg_frag(fa, vf, C3D, base, N, (c + 2) * KC, t);
                ldg_frag(fb, w1, C3D, 0, 1 << 30, (c + 2) * KC, t);
            }
            __syncthreads();
        }
    }
    store_tile(g_hpre, acc, b1, base, N, tr4, tc4);
}

// ---------------- stats over a [N,128] array ----------------
// src==nullptr => g_hpre (device-side symbol resolve; host-side symbol is
// an ATS-readable host shadow on GB300 => silent garbage)
__global__ __launch_bounds__(128) void k_stats(const float* src, int off,
                                               int N, int rpb) {
    if (src == nullptr) src = g_hpre;
    __shared__ float ss[128], sq[128];
    int t = threadIdx.x;
    ss[t] = 0.f; sq[t] = 0.f;
    __syncthreads();
    int q4 = (t & 31) * 4, rg = t >> 5;
    long r0 = (long)blockIdx.x * rpb;
    long r1 = r0 + rpb; if (r1 > N) r1 = N;
    float s0=0,s1=0,s2=0,s3=0, p0=0,p1=0,p2=0,p3=0;
    for (long r = r0 + rg; r < r1; r += 4) {
        float4 v = *reinterpret_cast<const float4*>(src + r * 128 + q4);
        s0 += v.x; s1 += v.y; s2 += v.z; s3 += v.w;
        p0 += v.x * v.x; p1 += v.y * v.y; p2 += v.z * v.z; p3 += v.w * v.w;
    }
    atomicAdd(&ss[q4], s0);     atomicAdd(&ss[q4 + 1], s1);
    atomicAdd(&ss[q4 + 2], s2); atomicAdd(&ss[q4 + 3], s3);
    atomicAdd(&sq[q4], p0);     atomicAdd(&sq[q4 + 1], p1);
    atomicAdd(&sq[q4 + 2], p2); atomicAdd(&sq[q4 + 3], p3);
    __syncthreads();
    atomicAdd(&g_stats[off + t], ss[t]);
    atomicAdd(&g_stats[off + 128 + t], sq[t]);
}

// ---------------- finalize bn stats ----------------
__global__ void k_fin(int which, const float* __restrict__ g,
                      const float* __restrict__ b, int N) {
    int j = threadIdx.x;
    int o = which * 256;
    float invN = 1.f / (float)N;
    float m   = g_stats[o + j] * invN;
    float msq = g_stats[o + 128 + j] * invN;
    float var = msq - m * m;
    float s = __ldg(g + j) * rsqrtf(var + 1e-5f);
    g_bnp[o + j] = s;
    g_bnp[o + 128 + j] = __ldg(b + j) - m * s;
}

// ---------------- K3: vfeat = relu(bn(hpre)) @ w2^T + b2 (double-buffered) ----------------
__global__ __launch_bounds__(256, 2) void k_gemm2(const float* __restrict__ w2,
                                                  const float* __restrict__ b2, int N) {
    __shared__ __align__(16) float sAT[2][KC][BM];
    __shared__ __align__(16) float sBT[2][KC][BM];
    __shared__ float sS[MID], sH[MID];
    GEMM_PROLOG();
    if (t < 128) { sS[t] = g_bnp[t]; sH[t] = g_bnp[128 + t]; }
    __syncthreads();
    const int nc = MID / KC;   // 8
    auto ldgA = [&](float4 f[2], int kofs) {
        ldg_frag(f, g_hpre, MID, base, N, kofs, t);
        #pragma unroll
        for (int i = 0; i < 2; i++) {
            int idx = i * 256 + t;
            int gk = kofs + (idx & 3) * 4;
            f[i].x = fmaxf(fmaf(f[i].x, sS[gk],     sH[gk]),     0.f);
            f[i].y = fmaxf(fmaf(f[i].y, sS[gk + 1], sH[gk + 1]), 0.f);
            f[i].z = fmaxf(fmaf(f[i].z, sS[gk + 2], sH[gk + 2]), 0.f);
            f[i].w = fmaxf(fmaf(f[i].w, sS[gk + 3], sH[gk + 3]), 0.f);
        }
    };
    float4 fa[2], fb[2];
    ldgA(fa, 0);
    ldg_frag(fb, w2, MID, 0, 1 << 30, 0, t);
    sts_frag(sAT[0], fa, t); sts_frag(sBT[0], fb, t);
    ldgA(fa, KC);
    ldg_frag(fb, w2, MID, 0, 1 << 30, KC, t);
    __syncthreads();
    for (int c = 0; c < nc; c++) {
        gemm_chunk(sAT[c & 1], sBT[c & 1], acc, tr4, tc4);
        if (c + 1 < nc) {
            sts_frag(sAT[(c + 1) & 1], fa, t); sts_frag(sBT[(c + 1) & 1], fb, t);
            if (c + 2 < nc) {
                ldgA(fa, (c + 2) * KC);
                ldg_frag(fb, w2, MID, 0, 1 << 30, (c + 2) * KC, t);
            }
            __syncthreads();
        }
    }
    store_tile(g_vfeat, acc, b2, base, N, tr4, tc4);
}

// ---------------- K4: projection + bilinear gather -> ifeat ----------------
__global__ __launch_bounds__(256) void k_sample(const int* __restrict__ coords,
                                                const float* __restrict__ P2, int N) {
    int j  = threadIdx.x & 127;
    int rr = threadIdx.x >> 7;
    int row0 = blockIdx.x * 64;
    for (int r = rr; r < 64; r += 2) {
        int row = row0 + r;
        if (row >= N) break;
        int4 c4 = __ldg(reinterpret_cast<const int4*>(coords + (size_t)row * 4));
        int b = c4.x;
        float p0 = (float)c4.y * 0.05f;
        float p1 = (float)c4.z * 0.05f - 40.f;
        float p2 = (float)c4.w * 0.1f  - 3.f;
        const float* P = P2 + b * 12;
        float cam0 = __ldg(P+0)*p0 + __ldg(P+1)*p1 + __ldg(P+2)*p2  + __ldg(P+3);
        float cam1 = __ldg(P+4)*p0 + __ldg(P+5)*p1 + __ldg(P+6)*p2  + __ldg(P+7);
        float cam2 = __ldg(P+8)*p0 + __ldg(P+9)*p1 + __ldg(P+10)*p2 + __ldg(P+11);
        float d = cam2 + 1e-8f;
        float u = cam0 / d;
        float v = cam1 / d;
        float gx = u / (float)W_ * 2.f - 1.f; gx = fminf(fmaxf(gx, -1.f), 1.f);
        float gy = v / (float)H_ * 2.f - 1.f; gy = fminf(fmaxf(gy, -1.f), 1.f);
        float ix = ((gx + 1.f) * (float)W_ - 1.f) * 0.5f;
        float iy = ((gy + 1.f) * (float)H_ - 1.f) * 0.5f;
        float x0f = floorf(ix), y0f = floorf(iy);
        float wx = ix - x0f, wy = iy - y0f;
        int x0 = (int)x0f, y0 = (int)y0f;
        float acc = 0.f;
        #pragma unroll
        for (int cy = 0; cy < 2; cy++) {
            #pragma unroll
            for (int cx = 0; cx < 2; cx++) {
                int yc = y0 + cy, xc = x0 + cx;
                float wgt = (cx ? wx : 1.f - wx) * (cy ? wy : 1.f - wy);
                if (xc >= 0 && xc < W_ && yc >= 0 && yc < H_) {
                    acc = fmaf(wgt,
                               g_imgT[(((size_t)(b * H_ + yc)) * W_ + xc) * C2D + j],
                               acc);
                }
            }
        }
        g_ifeat[(size_t)row * C2D + j] = acc;
    }
}

// shared A loader for the concat [vfeat | ifeat] inputs (att / fuse)
__device__ __forceinline__ void ldg_cat(float4 f[2], int base, int N, int ck, int t) {
    const float* src = (ck < 128) ? g_vfeat : g_ifeat;
    int ko = (ck < 128) ? ck : ck - 128;
    ldg_frag(f, src, 128, base, N, ko, t);
}

// ---------------- K5: attention scalar (double-buffered) ----------------
__global__ __launch_bounds__(256, 2) void k_att(const float* __restrict__ aw1,
                                                const float* __restrict__ ab1,
                                                const float* __restrict__ aw2,
                                                const float* __restrict__ ab2, int N) {
    __shared__ __align__(16) float sAT[2][KC][BM];
    __shared__ __align__(16) float sBT[2][KC][BM];
    __shared__ float sred[BM][17];
    GEMM_PROLOG();
    const int nc = 256 / KC;   // 16
    float4 fa[2], fb[2];
    ldg_cat(fa, base, N, 0, t);
    ldg_frag(fb, aw1, 256, 0, 1 << 30, 0, t);
    sts_frag(sAT[0], fa, t); sts_frag(sBT[0], fb, t);
    ldg_cat(fa, base, N, KC, t);
    ldg_frag(fb, aw1, 256, 0, 1 << 30, KC, t);
    __syncthreads();
    for (int c = 0; c < nc; c++) {
        gemm_chunk(sAT[c & 1], sBT[c & 1], acc, tr4, tc4);
        if (c + 1 < nc) {
            sts_frag(sAT[(c + 1) & 1], fa, t); sts_frag(sBT[(c + 1) & 1], fb, t);
            if (c + 2 < nc) {
                ldg_cat(fa, base, N, (c + 2) * KC, t);
                ldg_frag(fb, aw1, 256, 0, 1 << 30, (c + 2) * KC, t);
            }
            __syncthreads();
        }
    }
    float4 bb0 = *reinterpret_cast<const float4*>(ab1 + tc4);
    float4 bb1 = *reinterpret_cast<const float4*>(ab1 + tc4 + 64);
    float bv[8] = {bb0.x, bb0.y, bb0.z, bb0.w, bb1.x, bb1.y, bb1.z, bb1.w};
    float4 ww0 = *reinterpret_cast<const float4*>(aw2 + tc4);
    float4 ww1 = *reinterpret_cast<const float4*>(aw2 + tc4 + 64);
    float wv[8] = {ww0.x, ww0.y, ww0.z, ww0.w, ww1.x, ww1.y, ww1.z, ww1.w};
    #pragma unroll
    for (int p = 0; p < 4; p++) {
        int rl = (p < 2) ? tr4 + 2 * p : tr4 + 64 + 2 * (p - 2);
        float slo = 0.f, shi = 0.f;
        #pragma unroll
        for (int c = 0; c < 8; c++) {
            slo += fmaxf(ulo(acc[c][p]) + bv[c], 0.f) * wv[c];
            shi += fmaxf(uhi(acc[c][p]) + bv[c], 0.f) * wv[c];
        }
        sred[rl][t & 15]     = slo;
        sred[rl + 1][t & 15] = shi;
    }
    __syncthreads();
    if (t < 128 && base + t < N) {
        float s = __ldg(ab2);
        #pragma unroll
        for (int i = 0; i < 16; i++) s += sred[t][i];
        g_att[base + t] = 1.f / (1.f + expf(-s));
    }
}

// ---------------- K6: fused GEMM -> out_pre (double-buffered) ----------------
__global__ __launch_bounds__(256, 2) void k_fuse(const float* __restrict__ fw,
                                                 const float* __restrict__ fb,
                                                 float* __restrict__ out, int N) {
    __shared__ __align__(16) float sAT[2][KC][BM];
    __shared__ __align__(16) float sBT[2][KC][BM];
    __shared__ float sa[BM];
    GEMM_PROLOG();
    if (t < 128) sa[t] = (base + t < N) ? g_att[base + t] : 0.f;
    __syncthreads();
    const int nc = 256 / KC;   // 16
    auto ldgA = [&](float4 f[2], int ck) {
        ldg_cat(f, base, N, ck, t);
        bool isv = (ck < 128);
        #pragma unroll
        for (int i = 0; i < 2; i++) {
            int idx = i * 256 + t;
            int r = idx >> 2;
            float a = sa[r];
            float m = isv ? a : 1.f - a;
            f[i].x *= m; f[i].y *= m; f[i].z *= m; f[i].w *= m;
        }
    };
    float4 fa[2], fb2[2];
    ldgA(fa, 0);
    ldg_frag(fb2, fw, 256, 0, 1 << 30, 0, t);
    sts_frag(sAT[0], fa, t); sts_frag(sBT[0], fb2, t);
    ldgA(fa, KC);
    ldg_frag(fb2, fw, 256, 0, 1 << 30, KC, t);
    __syncthreads();
    for (int c = 0; c < nc; c++) {
        gemm_chunk(sAT[c & 1], sBT[c & 1], acc, tr4, tc4);
        if (c + 1 < nc) {
            sts_frag(sAT[(c + 1) & 1], fa, t); sts_frag(sBT[(c + 1) & 1], fb2, t);
            if (c + 2 < nc) {
                ldgA(fa, (c + 2) * KC);
                ldg_frag(fb2, fw, 256, 0, 1 << 30, (c + 2) * KC, t);
            }
            __syncthreads();
        }
    }
    store_tile(out, acc, fb, base, N, tr4, tc4);
}

// ---------------- K8: in-place final bn + relu ----------------
__global__ void k_bnrelu(float* __restrict__ out, long total4) {
    long i = (long)blockIdx.x * blockDim.x + threadIdx.x;
    if (i < total4) {
        int cb = (int)((i & 31) * 4);
        float4 v = reinterpret_cast<float4*>(out)[i];
        v.x = fmaxf(fmaf(v.x, g_bnp[256 + cb],     g_bnp[384 + cb]),     0.f);
        v.y = fmaxf(fmaf(v.y, g_bnp[256 + cb + 1], g_bnp[384 + cb + 1]), 0.f);
        v.z = fmaxf(fmaf(v.z, g_bnp[256 + cb + 2], g_bnp[384 + cb + 2]), 0.f);
        v.w = fmaxf(fmaf(v.w, g_bnp[256 + cb + 3], g_bnp[384 + cb + 3]), 0.f);
        reinterpret_cast<float4*>(out)[i] = v;
    }
}

// ---------------- launch ----------------
extern "C" void kernel_launch(void* const* d_in, const int* in_sizes, int n_in,
                              void* d_out, int out_size) {
    const float* vf     = (const float*)d_in[0];
    const int*   coords = (const int*)  d_in[1];
    const float* img    = (const float*)d_in[2];
    const float* P2     = (const float*)d_in[3];
    const float* vt_w1  = (const float*)d_in[4];
    const float* vt_b1  = (const float*)d_in[5];
    const float* bn1_g  = (const float*)d_in[6];
    const float* bn1_b  = (const float*)d_in[7];
    const float* vt_w2  = (const float*)d_in[8];
    const float* vt_b2  = (const float*)d_in[9];
    const float* att_w1 = (const float*)d_in[10];
    const float* att_b1 = (const float*)d_in[11];
    const float* att_w2 = (const float*)d_in[12];
    const float* att_b2 = (const float*)d_in[13];
    const float* fus_w  = (const float*)d_in[14];
    const float* fus_b  = (const float*)d_in[15];
    const float* bnf_g  = (const float*)d_in[16];
    const float* bnf_b  = (const float*)d_in[17];

    int N = in_sizes[1] / 4;
    float* out = (float*)d_out;
    int nblk = (N + BM - 1) / BM;
    int sblk = 512, rpb = (N + sblk - 1) / sblk;

    k_transpose<<<dim3((W_ + 31) / 32, C2D / 32, B_ * H_), dim3(32, 8)>>>(img);
    k_zero<<<1, 512>>>();
    k_gemm1<<<nblk, 256>>>(vf, vt_w1, vt_b1, N);
    k_stats<<<sblk, 128>>>(nullptr, 0, N, rpb);   // nullptr => g_hpre
    k_fin<<<1, 128>>>(0, bn1_g, bn1_b, N);
    k_gemm2<<<nblk, 256>>>(vt_w2, vt_b2, N);
    k_sample<<<(N + 63) / 64, 256>>>(coords, P2, N);
    k_att<<<nblk, 256>>>(att_w1, att_b1, att_w2, att_b2, N);
    k_fuse<<<nblk, 256>>>(fus_w, fus_b, out, N);
    k_stats<<<sblk, 128>>>(out, 256, N, rpb);
    k_fin<<<1, 128>>>(1, bnf_g, bnf_b, N);
    long total4 = (long)N * 32;
    k_bnrelu<<<(unsigned)((total4 + 255) / 256), 256>>>(out, total4);
}